// round 4
// baseline (speedup 1.0000x reference)
#include <cuda_runtime.h>
#include <math.h>
#include <float.h>

#define NB 32
#define NS 32768
#define NF 128
#define DM 128

// ------------------------- scratch (device globals) -------------------------
__device__ float2 g_x2[NB * NS];          // (hi, lo) tf32 split of x
__device__ float2 g_w2[128 * 512];        // (hi, lo) tf32 split of fb
__device__ float g_chunk[NB * NF * DM];   // pooled half-window sums (already /512)
__device__ float g_h[NB * NF * DM];
__device__ float g_qkv[NB * NF * 384];
__device__ float g_attno[NB * NF * DM];
__device__ float g_tmp[NB * NF * DM];
__device__ float g_ff[NB * NF * DM];
__device__ int   g_topidx[NB * 16];
__device__ float g_topval[NB * 16];

// ------------------------- helpers ------------------------------------------
__device__ __forceinline__ unsigned to_tf32(float x) {
    unsigned r; asm("cvt.rna.tf32.f32 %0, %1;" : "=r"(r) : "f"(x)); return r;
}

__device__ __forceinline__ void mma_tf32(float& d0, float& d1, float& d2, float& d3,
                                         unsigned a0, unsigned a1, unsigned a2, unsigned a3,
                                         unsigned b0, unsigned b1)
{
    asm volatile("mma.sync.aligned.m16n8k8.row.col.f32.tf32.tf32.f32 "
                 "{%0,%1,%2,%3}, {%4,%5,%6,%7}, {%8,%9}, {%0,%1,%2,%3};"
                 : "+f"(d0), "+f"(d1), "+f"(d2), "+f"(d3)
                 : "r"(a0), "r"(a1), "r"(a2), "r"(a3), "r"(b0), "r"(b1));
}

#define CP_ASYNC16(dst_smem, src) \
    asm volatile("cp.async.ca.shared.global [%0], [%1], 16;" :: "r"(dst_smem), "l"(src))
#define CP_COMMIT() asm volatile("cp.async.commit_group;")
#define CP_WAIT(n)  asm volatile("cp.async.wait_group %0;" :: "n"(n))

// ------------------------- tf32 split precompute -----------------------------
__global__ void split_x_kernel(const float* __restrict__ x) {
    int i = blockIdx.x * 256 + threadIdx.x;
    if (i < NB * NS) {
        float v = x[i];
        unsigned hb = to_tf32(v);
        float hi = __uint_as_float(hb);
        unsigned lb = to_tf32(v - hi);
        g_x2[i] = make_float2(hi, __uint_as_float(lb));
    }
}
__global__ void split_w_kernel(const float* __restrict__ fb) {
    int i = blockIdx.x * 256 + threadIdx.x;
    if (i < 128 * 512) {
        float v = fb[i];
        unsigned hb = to_tf32(v);
        float hi = __uint_as_float(hb);
        unsigned lb = to_tf32(v - hi);
        g_w2[i] = make_float2(hi, __uint_as_float(lb));
    }
}

// ------------------------- conv (3xTF32 mma) + |.| + pool --------------------
// Per block (h, b): y[t, c] = sum_k xwin[t+k] * w[c,k], t in [0,256), c in [0,128),
// then g_chunk[b,h,c] = sum_t |y| / 512.
#define WPAD 68                          // float2 per padded weight row
#define SLAB_F2 (128 * WPAD)             // one K=64 weight slab (padded)
#define CONV_SMEM ((2 * SLAB_F2 + 768) * 8 + 128 * 4)

__global__ __launch_bounds__(512, 1) void conv_mma_kernel(const float* __restrict__ dummy)
{
    extern __shared__ __align__(16) float2 smem2[];
    float2* ws[2] = { smem2, smem2 + SLAB_F2 };
    float2* xs2 = smem2 + 2 * SLAB_F2;               // 768 float2
    float* csum = (float*)(smem2 + 2 * SLAB_F2 + 768);

    const int h = blockIdx.x, b = blockIdx.y;
    const int tid = threadIdx.x;
    const int w = tid >> 5, lane = tid & 31;
    const int gid = lane >> 2, tig = lane & 3;
    const int tbase = (w >> 2) * 64;                 // warp t-tile
    const int cbase = (w & 3) * 32;                  // warp c-tile
    const int t0 = h << 8;

    // x window (hi,lo): global indices t0-256 .. t0+511
    const float2* xb = g_x2 + (size_t)b * NS;
    for (int i = tid; i < 768; i += 512) {
        int g = t0 - 256 + i;
        xs2[i] = (g >= 0 && g < NS) ? xb[g] : make_float2(0.f, 0.f);
    }
    if (tid < 128) csum[tid] = 0.f;

    // slab loader: K-slab s covers k in [64s, 64s+64)
    unsigned ws_base[2];
    ws_base[0] = (unsigned)__cvta_generic_to_shared(ws[0]);
    ws_base[1] = (unsigned)__cvta_generic_to_shared(ws[1]);
    auto load_slab = [&](int buf, int k0) {
        for (int q = tid; q < 4096; q += 512) {
            int c = q >> 5, j = q & 31;                       // j: pair of float2
            unsigned dst = ws_base[buf] + (unsigned)(c * WPAD + 2 * j) * 8;
            const float2* src = g_w2 + (size_t)c * 512 + k0 + 2 * j;
            CP_ASYNC16(dst, src);
        }
    };

    float d[4][4][4];
#pragma unroll
    for (int m = 0; m < 4; m++)
#pragma unroll
        for (int n = 0; n < 4; n++)
#pragma unroll
            for (int r = 0; r < 4; r++) d[m][n][r] = 0.f;

    load_slab(0, 0);
    CP_COMMIT();

    for (int s = 0; s < 8; s++) {
        if (s < 7) { load_slab((s + 1) & 1, (s + 1) * 64); CP_COMMIT(); CP_WAIT(1); }
        else       { CP_WAIT(0); }
        __syncthreads();
        const float2* wsb = ws[s & 1];
#pragma unroll
        for (int k8 = 0; k8 < 8; k8++) {
            const int kb = k8 * 8;
            unsigned bh0[4], bl0[4], bh1[4], bl1[4];
#pragma unroll
            for (int n = 0; n < 4; n++) {
                const float2* wr = wsb + (size_t)(cbase + 8 * n + gid) * WPAD + kb + tig;
                float2 v0 = wr[0];
                float2 v1 = wr[4];
                bh0[n] = __float_as_uint(v0.x); bl0[n] = __float_as_uint(v0.y);
                bh1[n] = __float_as_uint(v1.x); bl1[n] = __float_as_uint(v1.y);
            }
            const int ib = tbase + gid + 64 * s + kb + tig;
#pragma unroll
            for (int m = 0; m < 4; m++) {
                float2 va0 = xs2[ib + 16 * m];
                float2 va1 = xs2[ib + 16 * m + 8];
                float2 va2 = xs2[ib + 16 * m + 4];
                float2 va3 = xs2[ib + 16 * m + 12];
                unsigned ah0 = __float_as_uint(va0.x), al0 = __float_as_uint(va0.y);
                unsigned ah1 = __float_as_uint(va1.x), al1 = __float_as_uint(va1.y);
                unsigned ah2 = __float_as_uint(va2.x), al2 = __float_as_uint(va2.y);
                unsigned ah3 = __float_as_uint(va3.x), al3 = __float_as_uint(va3.y);
#pragma unroll
                for (int n = 0; n < 4; n++) {
                    mma_tf32(d[m][n][0], d[m][n][1], d[m][n][2], d[m][n][3],
                             ah0, ah1, ah2, ah3, bh0[n], bh1[n]);
                    mma_tf32(d[m][n][0], d[m][n][1], d[m][n][2], d[m][n][3],
                             ah0, ah1, ah2, ah3, bl0[n], bl1[n]);
                    mma_tf32(d[m][n][0], d[m][n][1], d[m][n][2], d[m][n][3],
                             al0, al1, al2, al3, bh0[n], bh1[n]);
                }
            }
        }
        __syncthreads();
    }

    // epilogue: abs + sum over t, pooled per channel
    float sacc[4][2];
#pragma unroll
    for (int n = 0; n < 4; n++) {
        sacc[n][0] = 0.f; sacc[n][1] = 0.f;
#pragma unroll
        for (int m = 0; m < 4; m++) {
            sacc[n][0] += fabsf(d[m][n][0]) + fabsf(d[m][n][2]);
            sacc[n][1] += fabsf(d[m][n][1]) + fabsf(d[m][n][3]);
        }
    }
    // reduce over gid (lane bits 2..4)
#pragma unroll
    for (int off = 4; off <= 16; off <<= 1)
#pragma unroll
        for (int n = 0; n < 4; n++) {
            sacc[n][0] += __shfl_xor_sync(0xffffffffu, sacc[n][0], off);
            sacc[n][1] += __shfl_xor_sync(0xffffffffu, sacc[n][1], off);
        }
    if (lane < 4) {
#pragma unroll
        for (int n = 0; n < 4; n++) {
            atomicAdd(&csum[cbase + 8 * n + 2 * tig + 0], sacc[n][0]);
            atomicAdd(&csum[cbase + 8 * n + 2 * tig + 1], sacc[n][1]);
        }
    }
    __syncthreads();
    if (tid < 128)
        g_chunk[((size_t)b * NF + h) * DM + tid] = csum[tid] * (1.f / 512.f);
}

// ---------------- frames + pos-encoding + embed -----------------------------
__global__ __launch_bounds__(128) void embed_kernel(const float* __restrict__ ew,
                                                    const float* __restrict__ eb)
{
    const int row = blockIdx.x;         // b*128 + t
    const int t = row & 127;
    const int tid = threadIdx.x;
    __shared__ float vec[161];
    {
        float f = g_chunk[(size_t)row * DM + tid];
        if (t > 0) f += g_chunk[(size_t)(row - 1) * DM + tid];
        vec[tid] = f;
    }
    if (tid < 33) {
        float pos = (t == 127) ? 1.0f
                               : __fadd_rn(-1.0f, __fmul_rn((float)t, __fdiv_rn(2.0f, 127.0f)));
        float v;
        if (tid == 0) v = pos;
        else {
            int k = (tid <= 16) ? (tid - 1) : (tid - 17);
            float fr = __fmul_rn(exp2f((float)k), 3.14159274101257324f);
            float prod = __fmul_rn(pos, fr);
            v = (tid <= 16) ? (float)sin((double)prod) : (float)cos((double)prod);
        }
        vec[128 + tid] = v;
    }
    __syncthreads();
    float a = eb[tid];
    const float* w = ew + (size_t)tid * 161;
    for (int j = 0; j < 161; j++) a = fmaf(vec[j], w[j], a);
    g_h[(size_t)row * DM + tid] = a;
}

// ---------------- generic row-blocked linear (K = 128) ----------------------
template <int NO, bool RELU>
__global__ __launch_bounds__(128) void linear_kernel(const float* __restrict__ in,
                                                     const float* __restrict__ W,
                                                     const float* __restrict__ bias,
                                                     float* __restrict__ out)
{
    const int row0 = blockIdx.x << 3;
    const int tid = threadIdx.x;
    __shared__ __align__(16) float sv[8 * DM];
#pragma unroll
    for (int r = 0; r < 8; r++) sv[r * DM + tid] = in[(size_t)(row0 + r) * DM + tid];
    __syncthreads();

    float acc[NO][8];
#pragma unroll
    for (int o = 0; o < NO; o++) {
        float bv = bias[o * DM + tid];
#pragma unroll
        for (int r = 0; r < 8; r++) acc[o][r] = bv;
    }
    const float4* sv4 = (const float4*)sv;
    const float4* W4 = (const float4*)W;
    for (int j4 = 0; j4 < 32; j4++) {
        float4 wv[NO];
#pragma unroll
        for (int o = 0; o < NO; o++) wv[o] = W4[(size_t)(o * DM + tid) * 32 + j4];
#pragma unroll
        for (int r = 0; r < 8; r++) {
            float4 xv = sv4[r * 32 + j4];
#pragma unroll
            for (int o = 0; o < NO; o++) {
                acc[o][r] = fmaf(wv[o].x, xv.x, acc[o][r]);
                acc[o][r] = fmaf(wv[o].y, xv.y, acc[o][r]);
                acc[o][r] = fmaf(wv[o].z, xv.z, acc[o][r]);
                acc[o][r] = fmaf(wv[o].w, xv.w, acc[o][r]);
            }
        }
    }
#pragma unroll
    for (int r = 0; r < 8; r++)
#pragma unroll
        for (int o = 0; o < NO; o++) {
            float v = acc[o][r];
            if (RELU) v = fmaxf(v, 0.f);
            out[(size_t)(row0 + r) * (NO * DM) + o * DM + tid] = v;
        }
}

// ---------------- attention (one block per (head, batch)) -------------------
__global__ __launch_bounds__(128) void attn_kernel()
{
    const int hd = blockIdx.x, b = blockIdx.y;
    const int tid = threadIdx.x;
    __shared__ __align__(16) float ks[NF * 32];
    __shared__ __align__(16) float vs[NF * 32];
    const float* base = g_qkv + (size_t)b * NF * 384;

    for (int idx = tid; idx < NF * 32; idx += 128) {
        int j = idx >> 5, i = idx & 31;
        ks[idx] = base[j * 384 + 128 + hd * 32 + i];
        vs[idx] = base[j * 384 + 256 + hd * 32 + i];
    }
    float q[32];
    {
        const float4* qp = (const float4*)(base + (size_t)tid * 384 + hd * 32);
#pragma unroll
        for (int i = 0; i < 8; i++) {
            float4 v = qp[i];
            q[4 * i] = v.x; q[4 * i + 1] = v.y; q[4 * i + 2] = v.z; q[4 * i + 3] = v.w;
        }
    }
    __syncthreads();

    float o[32];
#pragma unroll
    for (int i = 0; i < 32; i++) o[i] = 0.f;
    float m = -FLT_MAX, l = 0.f;
    const float scale = 0.17677669529663689f;

    for (int j = 0; j < NF; j++) {
        const float4* kp = (const float4*)(ks + j * 32);
        float s = 0.f;
#pragma unroll
        for (int i = 0; i < 8; i++) {
            float4 kv = kp[i];
            s = fmaf(q[4 * i], kv.x, s); s = fmaf(q[4 * i + 1], kv.y, s);
            s = fmaf(q[4 * i + 2], kv.z, s); s = fmaf(q[4 * i + 3], kv.w, s);
        }
        s *= scale;
        float mn = fmaxf(m, s);
        float c = expf(m - mn);
        float p = expf(s - mn);
        l = l * c + p;
        const float4* vp = (const float4*)(vs + j * 32);
#pragma unroll
        for (int i = 0; i < 8; i++) {
            float4 vv = vp[i];
            o[4 * i]     = o[4 * i] * c + p * vv.x;
            o[4 * i + 1] = o[4 * i + 1] * c + p * vv.y;
            o[4 * i + 2] = o[4 * i + 2] * c + p * vv.z;
            o[4 * i + 3] = o[4 * i + 3] * c + p * vv.w;
        }
        m = mn;
    }
    float inv = 1.f / l;
    float* dst = g_attno + (size_t)(b * NF + tid) * DM + hd * 32;
#pragma unroll
    for (int i = 0; i < 32; i++) dst[i] = o[i] * inv;
}

// ---------------- residual add + layernorm ----------------------------------
__global__ __launch_bounds__(128) void addln_kernel(float* __restrict__ hbuf,
                                                    const float* __restrict__ tbuf,
                                                    const float* __restrict__ w,
                                                    const float* __restrict__ bias)
{
    const int row = blockIdx.x, tid = threadIdx.x;
    __shared__ float sb[4];
    float v = hbuf[(size_t)row * DM + tid] + tbuf[(size_t)row * DM + tid];
    float s = v;
#pragma unroll
    for (int o = 16; o; o >>= 1) s += __shfl_xor_sync(0xffffffffu, s, o);
    if ((tid & 31) == 0) sb[tid >> 5] = s;
    __syncthreads();
    float mean = (sb[0] + sb[1] + sb[2] + sb[3]) * 0.0078125f;
    float dv = v - mean;
    float s2 = dv * dv;
#pragma unroll
    for (int o = 16; o; o >>= 1) s2 += __shfl_xor_sync(0xffffffffu, s2, o);
    __syncthreads();
    if ((tid & 31) == 0) sb[tid >> 5] = s2;
    __syncthreads();
    float var = (sb[0] + sb[1] + sb[2] + sb[3]) * 0.0078125f;
    float r = 1.f / sqrtf(var + 1e-5f);
    hbuf[(size_t)row * DM + tid] = dv * r * w[tid] + bias[tid];
}

// ---------------- attention scores + top-16 ---------------------------------
__global__ __launch_bounds__(128) void topk_kernel(const float* __restrict__ attn_w,
                                                   const float* __restrict__ attn_b)
{
    const int b = blockIdx.x, tid = threadIdx.x;
    __shared__ float sv[128];
    __shared__ float rv[128];
    __shared__ int ri[128];
    const float4* hp = (const float4*)(g_h + (size_t)(b * NF + tid) * DM);
    const float4* wp = (const float4*)attn_w;
    float s = attn_b[0];
#pragma unroll
    for (int i = 0; i < 32; i++) {
        float4 h4 = hp[i], w4 = wp[i];
        s = fmaf(h4.x, w4.x, s); s = fmaf(h4.y, w4.y, s);
        s = fmaf(h4.z, w4.z, s); s = fmaf(h4.w, w4.w, s);
    }
    sv[tid] = s;
    __syncthreads();
    for (int r = 0; r < 16; r++) {
        rv[tid] = sv[tid]; ri[tid] = tid;
        __syncthreads();
        for (int off = 64; off; off >>= 1) {
            if (tid < off) {
                float v2 = rv[tid + off]; int i2 = ri[tid + off];
                if (v2 > rv[tid] || (v2 == rv[tid] && i2 < ri[tid])) { rv[tid] = v2; ri[tid] = i2; }
            }
            __syncthreads();
        }
        if (tid == 0) {
            g_topidx[b * 16 + r] = ri[0];
            g_topval[b * 16 + r] = rv[0];
            sv[ri[0]] = -FLT_MAX;
        }
        __syncthreads();
    }
}

// ---------------- head: amp, pos/atom argmax, scatter -----------------------
__global__ __launch_bounds__(128) void scatter_kernel(const float* __restrict__ amp_w,
                                                      const float* __restrict__ amp_b,
                                                      const float* __restrict__ pos_w,
                                                      const float* __restrict__ pos_b,
                                                      const float* __restrict__ atom_w,
                                                      const float* __restrict__ atom_b,
                                                      const float* __restrict__ dmat,
                                                      float* __restrict__ out)
{
    const int rk = blockIdx.x, b = blockIdx.y, tid = threadIdx.x;
    __shared__ __align__(16) float vec[128];
    __shared__ float rv[128];
    __shared__ int ri[128];
    __shared__ float amp_s;
    __shared__ int jstar_s, astar_s;

    int id = g_topidx[b * 16 + rk];
    float val = g_topval[b * 16 + rk];
    vec[tid] = g_h[(size_t)(b * NF + id) * DM + tid] * val;
    __syncthreads();

    rv[tid] = vec[tid] * amp_w[tid];
    __syncthreads();
    for (int off = 64; off; off >>= 1) {
        if (tid < off) rv[tid] += rv[tid + off];
        __syncthreads();
    }
    if (tid == 0) amp_s = fmaxf(rv[0] + amp_b[0], 0.f);
    __syncthreads();

    const float4* vp = (const float4*)vec;

    float bv = -FLT_MAX; int bi = 1 << 30;
#pragma unroll
    for (int q = 0; q < 4; q++) {
        int o = q * 128 + tid;
        const float4* wp = (const float4*)(pos_w + (size_t)o * DM);
        float lg = pos_b[o];
#pragma unroll
        for (int i = 0; i < 32; i++) {
            float4 w4 = wp[i], v4 = vp[i];
            lg = fmaf(w4.x, v4.x, lg); lg = fmaf(w4.y, v4.y, lg);
            lg = fmaf(w4.z, v4.z, lg); lg = fmaf(w4.w, v4.w, lg);
        }
        if (lg > bv || (lg == bv && o < bi)) { bv = lg; bi = o; }
    }
    rv[tid] = bv; ri[tid] = bi;
    __syncthreads();
    for (int off = 64; off; off >>= 1) {
        if (tid < off) {
            float v2 = rv[tid + off]; int i2 = ri[tid + off];
            if (v2 > rv[tid] || (v2 == rv[tid] && i2 < ri[tid])) { rv[tid] = v2; ri[tid] = i2; }
        }
        __syncthreads();
    }
    if (tid == 0) jstar_s = ri[0];
    __syncthreads();

    bv = -FLT_MAX; bi = 1 << 30;
#pragma unroll
    for (int q = 0; q < 2; q++) {
        int o = q * 128 + tid;
        const float4* wp = (const float4*)(atom_w + (size_t)o * DM);
        float lg = atom_b[o];
#pragma unroll
        for (int i = 0; i < 32; i++) {
            float4 w4 = wp[i], v4 = vp[i];
            lg = fmaf(w4.x, v4.x, lg); lg = fmaf(w4.y, v4.y, lg);
            lg = fmaf(w4.z, v4.z, lg); lg = fmaf(w4.w, v4.w, lg);
        }
        if (lg > bv || (lg == bv && o < bi)) { bv = lg; bi = o; }
    }
    rv[tid] = bv; ri[tid] = bi;
    __syncthreads();
    for (int off = 64; off; off >>= 1) {
        if (tid < off) {
            float v2 = rv[tid + off]; int i2 = ri[tid + off];
            if (v2 > rv[tid] || (v2 == rv[tid] && i2 < ri[tid])) { rv[tid] = v2; ri[tid] = i2; }
        }
        __syncthreads();
    }
    if (tid == 0) astar_s = ri[0];
    __syncthreads();

    float amp = amp_s;
    int p = jstar_s * 64;
    int a = astar_s;
    for (int i = tid; i < 256; i += 128) {
        int t = p + i;
        if (t < NS)
            atomicAdd(out + (size_t)b * NS + t, dmat[(size_t)a * 256 + i] * amp);
    }
}

// ---------------------------------------------------------------------------
extern "C" void kernel_launch(void* const* d_in, const int* in_sizes, int n_in,
                              void* d_out, int out_size)
{
    const float* x         = (const float*)d_in[0];
    const float* fb        = (const float*)d_in[1];
    const float* embed_w   = (const float*)d_in[2];
    const float* embed_b   = (const float*)d_in[3];
    const float* in_proj_w = (const float*)d_in[4];
    const float* in_proj_b = (const float*)d_in[5];
    const float* out_w     = (const float*)d_in[6];
    const float* out_b     = (const float*)d_in[7];
    const float* lin1_w    = (const float*)d_in[8];
    const float* lin1_b    = (const float*)d_in[9];
    const float* lin2_w    = (const float*)d_in[10];
    const float* lin2_b    = (const float*)d_in[11];
    const float* ln1_w     = (const float*)d_in[12];
    const float* ln1_b     = (const float*)d_in[13];
    const float* ln2_w     = (const float*)d_in[14];
    const float* ln2_b     = (const float*)d_in[15];
    const float* attn_w    = (const float*)d_in[16];
    const float* attn_b    = (const float*)d_in[17];
    const float* amp_w     = (const float*)d_in[18];
    const float* amp_b     = (const float*)d_in[19];
    const float* pos_w     = (const float*)d_in[20];
    const float* pos_b     = (const float*)d_in[21];
    const float* atom_w    = (const float*)d_in[22];
    const float* atom_b    = (const float*)d_in[23];
    const float* dmat      = (const float*)d_in[24];
    float* out = (float*)d_out;

    float *p_h, *p_qkv, *p_attno, *p_tmp, *p_ff;
    cudaGetSymbolAddress((void**)&p_h, g_h);
    cudaGetSymbolAddress((void**)&p_qkv, g_qkv);
    cudaGetSymbolAddress((void**)&p_attno, g_attno);
    cudaGetSymbolAddress((void**)&p_tmp, g_tmp);
    cudaGetSymbolAddress((void**)&p_ff, g_ff);

    split_x_kernel<<<(NB * NS + 255) / 256, 256>>>(x);
    split_w_kernel<<<(128 * 512 + 255) / 256, 256>>>(fb);

    cudaFuncSetAttribute(conv_mma_kernel, cudaFuncAttributeMaxDynamicSharedMemorySize, CONV_SMEM);
    conv_mma_kernel<<<dim3(NF, NB), 512, CONV_SMEM>>>(x);

    embed_kernel<<<NB * NF, 128>>>(embed_w, embed_b);

    for (int i = 0; i < 6; i++) {
        linear_kernel<3, false><<<512, 128>>>(p_h, in_proj_w + (size_t)i * 384 * 128,
                                              in_proj_b + i * 384, p_qkv);
        attn_kernel<<<dim3(4, NB), 128>>>();
        linear_kernel<1, false><<<512, 128>>>(p_attno, out_w + (size_t)i * 128 * 128,
                                              out_b + i * 128, p_tmp);
        addln_kernel<<<NB * NF, 128>>>(p_h, p_tmp, ln1_w + i * 128, ln1_b + i * 128);
        linear_kernel<1, true><<<512, 128>>>(p_h, lin1_w + (size_t)i * 128 * 128,
                                             lin1_b + i * 128, p_ff);
        linear_kernel<1, false><<<512, 128>>>(p_ff, lin2_w + (size_t)i * 128 * 128,
                                              lin2_b + i * 128, p_tmp);
        addln_kernel<<<NB * NF, 128>>>(p_h, p_tmp, ln2_w + i * 128, ln2_b + i * 128);
    }

    topk_kernel<<<NB, 128>>>(attn_w, attn_b);
    cudaMemsetAsync(d_out, 0, (size_t)out_size * sizeof(float), 0);
    scatter_kernel<<<dim3(16, NB), 128>>>(amp_w, amp_b, pos_w, pos_b,
                                          atom_w, atom_b, dmat, out);
}

// round 6
// speedup vs baseline: 1.0486x; 1.0486x over previous
#include <cuda_runtime.h>
#include <math.h>
#include <float.h>

#define NB 32
#define NS 32768
#define NF 128
#define DM 128

// ------------------------- scratch (device globals) -------------------------
__device__ float2 g_x2[NB * NS];          // (hi, lo) tf32 split of x
__device__ float2 g_w2[128 * 512];        // (hi, lo) tf32 split of fb
__device__ float g_chunk[NB * NF * DM];
__device__ float g_h[NB * NF * DM];
__device__ float g_qkv[NB * NF * 384];
__device__ float g_attno[NB * NF * DM];
__device__ float g_tmp[NB * NF * DM];
__device__ int   g_topidx[NB * 16];
__device__ float g_topval[NB * 16];

// ------------------------- helpers ------------------------------------------
__device__ __forceinline__ unsigned to_tf32(float x) {
    unsigned r; asm("cvt.rna.tf32.f32 %0, %1;" : "=r"(r) : "f"(x)); return r;
}
__device__ __forceinline__ unsigned fu(float x) { return __float_as_uint(x); }

__device__ __forceinline__ void mma_tf32(float& d0, float& d1, float& d2, float& d3,
                                         unsigned a0, unsigned a1, unsigned a2, unsigned a3,
                                         unsigned b0, unsigned b1)
{
    asm volatile("mma.sync.aligned.m16n8k8.row.col.f32.tf32.tf32.f32 "
                 "{%0,%1,%2,%3}, {%4,%5,%6,%7}, {%8,%9}, {%0,%1,%2,%3};"
                 : "+f"(d0), "+f"(d1), "+f"(d2), "+f"(d3)
                 : "r"(a0), "r"(a1), "r"(a2), "r"(a3), "r"(b0), "r"(b1));
}

#define CP_ASYNC16(dst_smem, src) \
    asm volatile("cp.async.ca.shared.global [%0], [%1], 16;" :: "r"(dst_smem), "l"(src))
#define CP_COMMIT() asm volatile("cp.async.commit_group;")
#define CP_WAIT(n)  asm volatile("cp.async.wait_group %0;" :: "n"(n))

// ------------------------- tf32 split precompute -----------------------------
__global__ void split_x_kernel(const float* __restrict__ x) {
    int i = blockIdx.x * 256 + threadIdx.x;
    if (i < NB * NS) {
        float v = x[i];
        float hi = __uint_as_float(to_tf32(v));
        g_x2[i] = make_float2(hi, __uint_as_float(to_tf32(v - hi)));
    }
}
__global__ void split_w_kernel(const float* __restrict__ fb) {
    int i = blockIdx.x * 256 + threadIdx.x;
    if (i < 128 * 512) {
        float v = fb[i];
        float hi = __uint_as_float(to_tf32(v));
        g_w2[i] = make_float2(hi, __uint_as_float(to_tf32(v - hi)));
    }
}

// ------------------------- conv (3xTF32 mma, lean) ---------------------------
// Block (bx, by, b): t in [128 bx, +128), c in [64 by, +64).
// D[m, c] = sum_k xwin[m+k] * w[c,k], K=512 in 8 slabs of 64.
// chunk h = bx>>1 accumulated atomically (g_chunk pre-zeroed).
#define BPAD 66
#define SLABF2 (64 * BPAD)              // 4224 float2 per buffer
#define CONV_SMEM ((2 * SLABF2 + 640) * 8)

__global__ __launch_bounds__(256) void conv_mma2_kernel()
{
    extern __shared__ __align__(16) float2 smem2[];
    float2* wsB = smem2;                 // [2][64][BPAD]
    float2* xs  = smem2 + 2 * SLABF2;    // 640 window (hi,lo)

    const int bx = blockIdx.x, by = blockIdx.y, b = blockIdx.z;
    const int t0 = bx << 7, c0 = by << 6;
    const int tid = threadIdx.x, w = tid >> 5, lane = tid & 31;
    const int gid = lane >> 2, tig = lane & 3;
    const int tb = (w & 3) << 5, cw = (w >> 2) << 5;

    const float2* xg = g_x2 + (size_t)b * NS;
    for (int i = tid; i < 640; i += 256) {
        int g = t0 - 256 + i;
        xs[i] = (g >= 0 && g < NS) ? xg[g] : make_float2(0.f, 0.f);
    }

    unsigned bbase = (unsigned)__cvta_generic_to_shared(wsB);
    const float2* wsrc = g_w2 + (size_t)c0 * 512;

    // preload slab 0
    for (int o = tid; o < 2048; o += 256) {
        int row = o >> 5, kk = (o & 31) << 1;
        CP_ASYNC16(bbase + (unsigned)(row * BPAD + kk) * 8,
                   wsrc + (size_t)row * 512 + kk);
    }
    CP_COMMIT();
    __syncthreads();

    float d[2][4][4];
#pragma unroll
    for (int mi = 0; mi < 2; mi++)
#pragma unroll
        for (int n = 0; n < 4; n++)
#pragma unroll
            for (int r = 0; r < 4; r++) d[mi][n][r] = 0.f;

    for (int s = 0; s < 8; s++) {
        if (s < 7) {
            unsigned dst0 = bbase + (unsigned)(((s + 1) & 1) * SLABF2) * 8;
            const float2* src0 = wsrc + 64 * (s + 1);
            for (int o = tid; o < 2048; o += 256) {
                int row = o >> 5, kk = (o & 31) << 1;
                CP_ASYNC16(dst0 + (unsigned)(row * BPAD + kk) * 8,
                           src0 + (size_t)row * 512 + kk);
            }
            CP_COMMIT();
            CP_WAIT(1);
        } else {
            CP_WAIT(0);
        }
        __syncthreads();
        const float2* wb = wsB + (s & 1) * SLABF2;
#pragma unroll
        for (int k8 = 0; k8 < 8; k8++) {
            const int kb = k8 << 3;
            const int ib = tb + (s << 6) + kb + gid + tig;
            float2 a0[2], a1[2], a2[2], a3[2];
#pragma unroll
            for (int mi = 0; mi < 2; mi++) {
                a0[mi] = xs[ib + (mi << 4)];
                a1[mi] = xs[ib + (mi << 4) + 8];
                a2[mi] = xs[ib + (mi << 4) + 4];
                a3[mi] = xs[ib + (mi << 4) + 12];
            }
#pragma unroll
            for (int n = 0; n < 4; n++) {
                const float2* wr = wb + (size_t)(cw + (n << 3) + gid) * BPAD + kb + tig;
                float2 B0 = wr[0], B1 = wr[4];
                unsigned bh0 = fu(B0.x), bl0 = fu(B0.y);
                unsigned bh1 = fu(B1.x), bl1 = fu(B1.y);
#pragma unroll
                for (int mi = 0; mi < 2; mi++) {
                    unsigned ah0 = fu(a0[mi].x), ah1 = fu(a1[mi].x);
                    unsigned ah2 = fu(a2[mi].x), ah3 = fu(a3[mi].x);
                    unsigned al0 = fu(a0[mi].y), al1 = fu(a1[mi].y);
                    unsigned al2 = fu(a2[mi].y), al3 = fu(a3[mi].y);
                    mma_tf32(d[mi][n][0], d[mi][n][1], d[mi][n][2], d[mi][n][3],
                             ah0, ah1, ah2, ah3, bh0, bh1);
                    mma_tf32(d[mi][n][0], d[mi][n][1], d[mi][n][2], d[mi][n][3],
                             ah0, ah1, ah2, ah3, bl0, bl1);
                    mma_tf32(d[mi][n][0], d[mi][n][1], d[mi][n][2], d[mi][n][3],
                             al0, al1, al2, al3, bh0, bh1);
                }
            }
        }
        __syncthreads();
    }

    // epilogue: |.| + sum over m, per column
    float cs[4][2];
#pragma unroll
    for (int n = 0; n < 4; n++) {
        cs[n][0] = 0.f; cs[n][1] = 0.f;
#pragma unroll
        for (int mi = 0; mi < 2; mi++) {
            cs[n][0] += fabsf(d[mi][n][0]) + fabsf(d[mi][n][2]);
            cs[n][1] += fabsf(d[mi][n][1]) + fabsf(d[mi][n][3]);
        }
    }
#pragma unroll
    for (int off = 4; off <= 16; off <<= 1)
#pragma unroll
        for (int n = 0; n < 4; n++) {
            cs[n][0] += __shfl_xor_sync(0xffffffffu, cs[n][0], off);
            cs[n][1] += __shfl_xor_sync(0xffffffffu, cs[n][1], off);
        }
    if (lane < 4) {
        float* base = g_chunk + ((size_t)b * NF + (bx >> 1)) * DM + c0 + cw;
#pragma unroll
        for (int n = 0; n < 4; n++) {
            atomicAdd(base + (n << 3) + 2 * tig,     cs[n][0] * (1.f / 512.f));
            atomicAdd(base + (n << 3) + 2 * tig + 1, cs[n][1] * (1.f / 512.f));
        }
    }
}

// ---------------- frames + pos-encoding + embed -----------------------------
__global__ __launch_bounds__(128) void embed_kernel(const float* __restrict__ ew,
                                                    const float* __restrict__ eb)
{
    const int row = blockIdx.x;         // b*128 + t
    const int t = row & 127;
    const int tid = threadIdx.x;
    __shared__ float vec[161];
    {
        float f = g_chunk[(size_t)row * DM + tid];
        if (t > 0) f += g_chunk[(size_t)(row - 1) * DM + tid];
        vec[tid] = f;
    }
    if (tid < 33) {
        float pos = (t == 127) ? 1.0f
                               : __fadd_rn(-1.0f, __fmul_rn((float)t, __fdiv_rn(2.0f, 127.0f)));
        float v;
        if (tid == 0) v = pos;
        else {
            int k = (tid <= 16) ? (tid - 1) : (tid - 17);
            float fr = __fmul_rn(exp2f((float)k), 3.14159274101257324f);
            float prod = __fmul_rn(pos, fr);
            v = (tid <= 16) ? (float)sin((double)prod) : (float)cos((double)prod);
        }
        vec[128 + tid] = v;
    }
    __syncthreads();
    const float* w = ew + (size_t)tid * 161;
    float a0 = eb[tid], a1 = 0.f, a2 = 0.f, a3 = 0.f;
    int j = 0;
#pragma unroll 10
    for (; j + 4 <= 161; j += 4) {
        a0 = fmaf(vec[j],     w[j],     a0);
        a1 = fmaf(vec[j + 1], w[j + 1], a1);
        a2 = fmaf(vec[j + 2], w[j + 2], a2);
        a3 = fmaf(vec[j + 3], w[j + 3], a3);
    }
    for (; j < 161; j++) a0 = fmaf(vec[j], w[j], a0);
    g_h[(size_t)row * DM + tid] = (a0 + a1) + (a2 + a3);
}

// ---------------- generic row-blocked linear (K = 128) ----------------------
template <int NO, bool RELU>
__global__ __launch_bounds__(128) void linear_kernel(const float* __restrict__ in,
                                                     const float* __restrict__ W,
                                                     const float* __restrict__ bias,
                                                     float* __restrict__ out)
{
    const int row0 = blockIdx.x << 3;
    const int tid = threadIdx.x;
    __shared__ __align__(16) float sv[8 * DM];
#pragma unroll
    for (int r = 0; r < 8; r++) sv[r * DM + tid] = in[(size_t)(row0 + r) * DM + tid];
    __syncthreads();

    float acc[NO][8];
#pragma unroll
    for (int o = 0; o < NO; o++) {
        float bv = bias[o * DM + tid];
#pragma unroll
        for (int r = 0; r < 8; r++) acc[o][r] = bv;
    }
    const float4* sv4 = (const float4*)sv;
    const float4* W4 = (const float4*)W;
    for (int j4 = 0; j4 < 32; j4++) {
        float4 wv[NO];
#pragma unroll
        for (int o = 0; o < NO; o++) wv[o] = W4[(size_t)(o * DM + tid) * 32 + j4];
#pragma unroll
        for (int r = 0; r < 8; r++) {
            float4 xv = sv4[r * 32 + j4];
#pragma unroll
            for (int o = 0; o < NO; o++) {
                acc[o][r] = fmaf(wv[o].x, xv.x, acc[o][r]);
                acc[o][r] = fmaf(wv[o].y, xv.y, acc[o][r]);
                acc[o][r] = fmaf(wv[o].z, xv.z, acc[o][r]);
                acc[o][r] = fmaf(wv[o].w, xv.w, acc[o][r]);
            }
        }
    }
#pragma unroll
    for (int r = 0; r < 8; r++)
#pragma unroll
        for (int o = 0; o < NO; o++) {
            float v = acc[o][r];
            if (RELU) v = fmaxf(v, 0.f);
            out[(size_t)(row0 + r) * (NO * DM) + o * DM + tid] = v;
        }
}

// ---------------- fused FFN: relu(h@W1^T+b1)@W2^T+b2 ------------------------
__global__ __launch_bounds__(128) void ff_kernel(const float* __restrict__ in,
                                                 const float* __restrict__ W1,
                                                 const float* __restrict__ b1,
                                                 const float* __restrict__ W2,
                                                 const float* __restrict__ b2,
                                                 float* __restrict__ out)
{
    const int row0 = blockIdx.x << 3;
    const int tid = threadIdx.x;
    __shared__ __align__(16) float sv[8 * DM];
    __shared__ __align__(16) float s1[8 * DM];
#pragma unroll
    for (int r = 0; r < 8; r++) sv[r * DM + tid] = in[(size_t)(row0 + r) * DM + tid];
    __syncthreads();

    float acc[8];
    {
        float bv = b1[tid];
#pragma unroll
        for (int r = 0; r < 8; r++) acc[r] = bv;
        const float4* sv4 = (const float4*)sv;
        const float4* W4 = (const float4*)W1;
        for (int j4 = 0; j4 < 32; j4++) {
            float4 wv = W4[(size_t)tid * 32 + j4];
#pragma unroll
            for (int r = 0; r < 8; r++) {
                float4 xv = sv4[r * 32 + j4];
                acc[r] = fmaf(wv.x, xv.x, acc[r]);
                acc[r] = fmaf(wv.y, xv.y, acc[r]);
                acc[r] = fmaf(wv.z, xv.z, acc[r]);
                acc[r] = fmaf(wv.w, xv.w, acc[r]);
            }
        }
    }
#pragma unroll
    for (int r = 0; r < 8; r++) s1[r * DM + tid] = fmaxf(acc[r], 0.f);
    __syncthreads();
    {
        float bv = b2[tid];
#pragma unroll
        for (int r = 0; r < 8; r++) acc[r] = bv;
        const float4* s14 = (const float4*)s1;
        const float4* W4 = (const float4*)W2;
        for (int j4 = 0; j4 < 32; j4++) {
            float4 wv = W4[(size_t)tid * 32 + j4];
#pragma unroll
            for (int r = 0; r < 8; r++) {
                float4 xv = s14[r * 32 + j4];
                acc[r] = fmaf(wv.x, xv.x, acc[r]);
                acc[r] = fmaf(wv.y, xv.y, acc[r]);
                acc[r] = fmaf(wv.z, xv.z, acc[r]);
                acc[r] = fmaf(wv.w, xv.w, acc[r]);
            }
        }
    }
#pragma unroll
    for (int r = 0; r < 8; r++) out[(size_t)(row0 + r) * DM + tid] = acc[r];
}

// ---------------- attention (one block per (head, batch)) -------------------
__global__ __launch_bounds__(128) void attn_kernel()
{
    const int hd = blockIdx.x, b = blockIdx.y;
    const int tid = threadIdx.x;
    __shared__ __align__(16) float ks[NF * 32];
    __shared__ __align__(16) float vs[NF * 32];
    const float* base = g_qkv + (size_t)b * NF * 384;

    for (int idx = tid; idx < NF * 32; idx += 128) {
        int j = idx >> 5, i = idx & 31;
        ks[idx] = base[j * 384 + 128 + hd * 32 + i];
        vs[idx] = base[j * 384 + 256 + hd * 32 + i];
    }
    float q[32];
    {
        const float4* qp = (const float4*)(base + (size_t)tid * 384 + hd * 32);
#pragma unroll
        for (int i = 0; i < 8; i++) {
            float4 v = qp[i];
            q[4 * i] = v.x; q[4 * i + 1] = v.y; q[4 * i + 2] = v.z; q[4 * i + 3] = v.w;
        }
    }
    __syncthreads();

    float o[32];
#pragma unroll
    for (int i = 0; i < 32; i++) o[i] = 0.f;
    float m = -FLT_MAX, l = 0.f;
    const float scale = 0.17677669529663689f;

    for (int j = 0; j < NF; j++) {
        const float4* kp = (const float4*)(ks + j * 32);
        float s = 0.f;
#pragma unroll
        for (int i = 0; i < 8; i++) {
            float4 kv = kp[i];
            s = fmaf(q[4 * i], kv.x, s); s = fmaf(q[4 * i + 1], kv.y, s);
            s = fmaf(q[4 * i + 2], kv.z, s); s = fmaf(q[4 * i + 3], kv.w, s);
        }
        s *= scale;
        float mn = fmaxf(m, s);
        float c = expf(m - mn);
        float p = expf(s - mn);
        l = l * c + p;
        const float4* vp = (const float4*)(vs + j * 32);
#pragma unroll
        for (int i = 0; i < 8; i++) {
            float4 vv = vp[i];
            o[4 * i]     = o[4 * i] * c + p * vv.x;
            o[4 * i + 1] = o[4 * i + 1] * c + p * vv.y;
            o[4 * i + 2] = o[4 * i + 2] * c + p * vv.z;
            o[4 * i + 3] = o[4 * i + 3] * c + p * vv.w;
        }
        m = mn;
    }
    float inv = 1.f / l;
    float* dst = g_attno + (size_t)(b * NF + tid) * DM + hd * 32;
#pragma unroll
    for (int i = 0; i < 32; i++) dst[i] = o[i] * inv;
}

// ---------------- residual add + layernorm ----------------------------------
__global__ __launch_bounds__(128) void addln_kernel(float* __restrict__ hbuf,
                                                    const float* __restrict__ tbuf,
                                                    const float* __restrict__ w,
                                                    const float* __restrict__ bias)
{
    const int row = blockIdx.x, tid = threadIdx.x;
    __shared__ float sb[4];
    float v = hbuf[(size_t)row * DM + tid] + tbuf[(size_t)row * DM + tid];
    float s = v;
#pragma unroll
    for (int o = 16; o; o >>= 1) s += __shfl_xor_sync(0xffffffffu, s, o);
    if ((tid & 31) == 0) sb[tid >> 5] = s;
    __syncthreads();
    float mean = (sb[0] + sb[1] + sb[2] + sb[3]) * 0.0078125f;
    float dv = v - mean;
    float s2 = dv * dv;
#pragma unroll
    for (int o = 16; o; o >>= 1) s2 += __shfl_xor_sync(0xffffffffu, s2, o);
    __syncthreads();
    if ((tid & 31) == 0) sb[tid >> 5] = s2;
    __syncthreads();
    float var = (sb[0] + sb[1] + sb[2] + sb[3]) * 0.0078125f;
    float r = 1.f / sqrtf(var + 1e-5f);
    hbuf[(size_t)row * DM + tid] = dv * r * w[tid] + bias[tid];
}

// ---------------- attention scores + top-16 ---------------------------------
__global__ __launch_bounds__(128) void topk_kernel(const float* __restrict__ attn_w,
                                                   const float* __restrict__ attn_b)
{
    const int b = blockIdx.x, tid = threadIdx.x;
    __shared__ float sv[128];
    __shared__ float rv[128];
    __shared__ int ri[128];
    const float4* hp = (const float4*)(g_h + (size_t)(b * NF + tid) * DM);
    const float4* wp = (const float4*)attn_w;
    float s = attn_b[0];
#pragma unroll
    for (int i = 0; i < 32; i++) {
        float4 h4 = hp[i], w4 = wp[i];
        s = fmaf(h4.x, w4.x, s); s = fmaf(h4.y, w4.y, s);
        s = fmaf(h4.z, w4.z, s); s = fmaf(h4.w, w4.w, s);
    }
    sv[tid] = s;
    __syncthreads();
    for (int r = 0; r < 16; r++) {
        rv[tid] = sv[tid]; ri[tid] = tid;
        __syncthreads();
        for (int off = 64; off; off >>= 1) {
            if (tid < off) {
                float v2 = rv[tid + off]; int i2 = ri[tid + off];
                if (v2 > rv[tid] || (v2 == rv[tid] && i2 < ri[tid])) { rv[tid] = v2; ri[tid] = i2; }
            }
            __syncthreads();
        }
        if (tid == 0) {
            g_topidx[b * 16 + r] = ri[0];
            g_topval[b * 16 + r] = rv[0];
            sv[ri[0]] = -FLT_MAX;
        }
        __syncthreads();
    }
}

// ---------------- head: amp, pos/atom argmax, scatter -----------------------
__global__ __launch_bounds__(128) void scatter_kernel(const float* __restrict__ amp_w,
                                                      const float* __restrict__ amp_b,
                                                      const float* __restrict__ pos_w,
                                                      const float* __restrict__ pos_b,
                                                      const float* __restrict__ atom_w,
                                                      const float* __restrict__ atom_b,
                                                      const float* __restrict__ dmat,
                                                      float* __restrict__ out)
{
    const int rk = blockIdx.x, b = blockIdx.y, tid = threadIdx.x;
    __shared__ __align__(16) float vec[128];
    __shared__ float rv[128];
    __shared__ int ri[128];
    __shared__ float amp_s;
    __shared__ int jstar_s, astar_s;

    int id = g_topidx[b * 16 + rk];
    float val = g_topval[b * 16 + rk];
    vec[tid] = g_h[(size_t)(b * NF + id) * DM + tid] * val;
    __syncthreads();

    rv[tid] = vec[tid] * amp_w[tid];
    __syncthreads();
    for (int off = 64; off; off >>= 1) {
        if (tid < off) rv[tid] += rv[tid + off];
        __syncthreads();
    }
    if (tid == 0) amp_s = fmaxf(rv[0] + amp_b[0], 0.f);
    __syncthreads();

    const float4* vp = (const float4*)vec;

    float bv = -FLT_MAX; int bi = 1 << 30;
#pragma unroll
    for (int q = 0; q < 4; q++) {
        int o = q * 128 + tid;
        const float4* wp = (const float4*)(pos_w + (size_t)o * DM);
        float lg = pos_b[o];
#pragma unroll
        for (int i = 0; i < 32; i++) {
            float4 w4 = wp[i], v4 = vp[i];
            lg = fmaf(w4.x, v4.x, lg); lg = fmaf(w4.y, v4.y, lg);
            lg = fmaf(w4.z, v4.z, lg); lg = fmaf(w4.w, v4.w, lg);
        }
        if (lg > bv || (lg == bv && o < bi)) { bv = lg; bi = o; }
    }
    rv[tid] = bv; ri[tid] = bi;
    __syncthreads();
    for (int off = 64; off; off >>= 1) {
        if (tid < off) {
            float v2 = rv[tid + off]; int i2 = ri[tid + off];
            if (v2 > rv[tid] || (v2 == rv[tid] && i2 < ri[tid])) { rv[tid] = v2; ri[tid] = i2; }
        }
        __syncthreads();
    }
    if (tid == 0) jstar_s = ri[0];
    __syncthreads();

    bv = -FLT_MAX; bi = 1 << 30;
#pragma unroll
    for (int q = 0; q < 2; q++) {
        int o = q * 128 + tid;
        const float4* wp = (const float4*)(atom_w + (size_t)o * DM);
        float lg = atom_b[o];
#pragma unroll
        for (int i = 0; i < 32; i++) {
            float4 w4 = wp[i], v4 = vp[i];
            lg = fmaf(w4.x, v4.x, lg); lg = fmaf(w4.y, v4.y, lg);
            lg = fmaf(w4.z, v4.z, lg); lg = fmaf(w4.w, v4.w, lg);
        }
        if (lg > bv || (lg == bv && o < bi)) { bv = lg; bi = o; }
    }
    rv[tid] = bv; ri[tid] = bi;
    __syncthreads();
    for (int off = 64; off; off >>= 1) {
        if (tid < off) {
            float v2 = rv[tid + off]; int i2 = ri[tid + off];
            if (v2 > rv[tid] || (v2 == rv[tid] && i2 < ri[tid])) { rv[tid] = v2; ri[tid] = i2; }
        }
        __syncthreads();
    }
    if (tid == 0) astar_s = ri[0];
    __syncthreads();

    float amp = amp_s;
    int p = jstar_s * 64;
    int a = astar_s;
    for (int i = tid; i < 256; i += 128) {
        int t = p + i;
        if (t < NS)
            atomicAdd(out + (size_t)b * NS + t, dmat[(size_t)a * 256 + i] * amp);
    }
}

// ---------------------------------------------------------------------------
extern "C" void kernel_launch(void* const* d_in, const int* in_sizes, int n_in,
                              void* d_out, int out_size)
{
    const float* x         = (const float*)d_in[0];
    const float* fb        = (const float*)d_in[1];
    const float* embed_w   = (const float*)d_in[2];
    const float* embed_b   = (const float*)d_in[3];
    const float* in_proj_w = (const float*)d_in[4];
    const float* in_proj_b = (const float*)d_in[5];
    const float* out_w     = (const float*)d_in[6];
    const float* out_b     = (const float*)d_in[7];
    const float* lin1_w    = (const float*)d_in[8];
    const float* lin1_b    = (const float*)d_in[9];
    const float* lin2_w    = (const float*)d_in[10];
    const float* lin2_b    = (const float*)d_in[11];
    const float* ln1_w     = (const float*)d_in[12];
    const float* ln1_b     = (const float*)d_in[13];
    const float* ln2_w     = (const float*)d_in[14];
    const float* ln2_b     = (const float*)d_in[15];
    const float* attn_w    = (const float*)d_in[16];
    const float* attn_b    = (const float*)d_in[17];
    const float* amp_w     = (const float*)d_in[18];
    const float* amp_b     = (const float*)d_in[19];
    const float* pos_w     = (const float*)d_in[20];
    const float* pos_b     = (const float*)d_in[21];
    const float* atom_w    = (const float*)d_in[22];
    const float* atom_b    = (const float*)d_in[23];
    const float* dmat      = (const float*)d_in[24];
    float* out = (float*)d_out;

    float *p_h, *p_qkv, *p_attno, *p_tmp, *p_chunk;
    cudaGetSymbolAddress((void**)&p_h, g_h);
    cudaGetSymbolAddress((void**)&p_qkv, g_qkv);
    cudaGetSymbolAddress((void**)&p_attno, g_attno);
    cudaGetSymbolAddress((void**)&p_tmp, g_tmp);
    cudaGetSymbolAddress((void**)&p_chunk, g_chunk);

    split_x_kernel<<<(NB * NS + 255) / 256, 256>>>(x);
    split_w_kernel<<<(128 * 512 + 255) / 256, 256>>>(fb);
    cudaMemsetAsync(p_chunk, 0, (size_t)NB * NF * DM * sizeof(float), 0);

    cudaFuncSetAttribute(conv_mma2_kernel, cudaFuncAttributeMaxDynamicSharedMemorySize, CONV_SMEM);
    conv_mma2_kernel<<<dim3(256, 2, NB), 256, CONV_SMEM>>>();

    embed_kernel<<<NB * NF, 128>>>(embed_w, embed_b);

    for (int i = 0; i < 6; i++) {
        linear_kernel<3, false><<<512, 128>>>(p_h, in_proj_w + (size_t)i * 384 * 128,
                                              in_proj_b + i * 384, p_qkv);
        attn_kernel<<<dim3(4, NB), 128>>>();
        linear_kernel<1, false><<<512, 128>>>(p_attno, out_w + (size_t)i * 128 * 128,
                                              out_b + i * 128, p_tmp);
        addln_kernel<<<NB * NF, 128>>>(p_h, p_tmp, ln1_w + i * 128, ln1_b + i * 128);
        ff_kernel<<<512, 128>>>(p_h, lin1_w + (size_t)i * 128 * 128, lin1_b + i * 128,
                                lin2_w + (size_t)i * 128 * 128, lin2_b + i * 128, p_tmp);
        addln_kernel<<<NB * NF, 128>>>(p_h, p_tmp, ln2_w + i * 128, ln2_b + i * 128);
    }

    topk_kernel<<<NB, 128>>>(attn_w, attn_b);
    cudaMemsetAsync(d_out, 0, (size_t)out_size * sizeof(float), 0);
    scatter_kernel<<<dim3(16, NB), 128>>>(amp_w, amp_b, pos_w, pos_b,
                                          atom_w, atom_b, dmat, out);
}

// round 7
// speedup vs baseline: 1.4273x; 1.3611x over previous
#include <cuda_runtime.h>
#include <math.h>
#include <float.h>

#define NB 32
#define NS 32768
#define NF 128
#define DM 128

// ------------------------- scratch (device globals) -------------------------
__device__ float2 g_twid[512];            // exp(-2*pi*i*k/1024)
__device__ float2 g_P[64 * 1024];         // conj(FFT(w_2c - i w_2c+1)), scrambled
__device__ float g_chunk[NB * NF * DM];
__device__ float g_h[NB * NF * DM];
__device__ float g_qkv[NB * NF * 384];
__device__ float g_attno[NB * NF * DM];
__device__ int   g_topidx[NB * 16];
__device__ float g_topval[NB * 16];

// ------------------------- FFT device functions ------------------------------
// DIF (Gentleman-Sande): natural in -> bit-reversed out. 256 threads, 4 pts/thr.
__device__ __forceinline__ void fft_dif(float* re, float* im, const float2* tw, int tid)
{
#pragma unroll
    for (int m = 512; m >= 2; m /= 4) {
        const int half = m >> 1;
        const int q = tid / half, r = tid % half;
        const int i0 = q * 2 * m + r;
        float ar = re[i0],            ai = im[i0];
        float br = re[i0 + half],     bi = im[i0 + half];
        float cr = re[i0 + m],        ci = im[i0 + m];
        float dr = re[i0 + m + half], di = im[i0 + m + half];
        // stage span m: pairs (a,c) tw[r*512/m], (b,d) tw[(r+half)*512/m]
        float2 w1 = tw[r * (512 / m)];
        float2 w2 = tw[(r + half) * (512 / m)];
        float t1r = ar - cr, t1i = ai - ci;
        ar += cr; ai += ci;
        cr = t1r * w1.x - t1i * w1.y; ci = t1r * w1.y + t1i * w1.x;
        float t2r = br - dr, t2i = bi - di;
        br += dr; bi += di;
        dr = t2r * w2.x - t2i * w2.y; di = t2r * w2.y + t2i * w2.x;
        // stage span half: pairs (a,b), (c,d), tw v = tab[r*1024/m]
        float2 v = tw[r * (1024 / m)];
        float s1r = ar - br, s1i = ai - bi;
        ar += br; ai += bi;
        br = s1r * v.x - s1i * v.y; bi = s1r * v.y + s1i * v.x;
        float s2r = cr - dr, s2i = ci - di;
        cr += dr; ci += di;
        dr = s2r * v.x - s2i * v.y; di = s2r * v.y + s2i * v.x;
        __syncthreads();
        re[i0] = ar;            im[i0] = ai;
        re[i0 + half] = br;     im[i0 + half] = bi;
        re[i0 + m] = cr;        im[i0 + m] = ci;
        re[i0 + m + half] = dr; im[i0 + m + half] = di;
        __syncthreads();
    }
}

// DIT (Cooley-Tukey) inverse: bit-reversed in -> natural out (unscaled).
__device__ __forceinline__ void ifft_dit(float* re, float* im, const float2* tw, int tid)
{
#pragma unroll
    for (int half = 1; half <= 256; half *= 4) {
        const int m = half << 1;
        const int q = tid / half, r = tid % half;
        const int i0 = q * 2 * m + r;
        float ar = re[i0],            ai = im[i0];
        float br = re[i0 + half],     bi = im[i0 + half];
        float cr = re[i0 + m],        ci = im[i0 + m];
        float dr = re[i0 + m + half], di = im[i0 + m + half];
        // stage span half: pairs (a,b), (c,d); twiddle conj(tw[r*512/half])
        float2 u = tw[r * (512 / half)];
        float tbr = br * u.x + bi * u.y, tbi = bi * u.x - br * u.y;
        br = ar - tbr; bi = ai - tbi; ar += tbr; ai += tbi;
        float tdr = dr * u.x + di * u.y, tdi = di * u.x - dr * u.y;
        dr = cr - tdr; di = ci - tdi; cr += tdr; ci += tdi;
        // stage span m: pairs (a,c) conj(tw[r*512/m]), (b,d) conj(tw[(r+half)*512/m])
        float2 t1 = tw[r * (512 / m)];
        float2 t2 = tw[(r + half) * (512 / m)];
        float tcr = cr * t1.x + ci * t1.y, tci = ci * t1.x - cr * t1.y;
        cr = ar - tcr; ci = ai - tci; ar += tcr; ai += tci;
        float tdr2 = dr * t2.x + di * t2.y, tdi2 = di * t2.x - dr * t2.y;
        dr = br - tdr2; di = bi - tdi2; br += tdr2; bi += tdi2;
        __syncthreads();
        re[i0] = ar;            im[i0] = ai;
        re[i0 + half] = br;     im[i0 + half] = bi;
        re[i0 + m] = cr;        im[i0 + m] = ci;
        re[i0 + m + half] = dr; im[i0 + m + half] = di;
        __syncthreads();
    }
}

// ------------------------- precompute kernels --------------------------------
__global__ void twid_kernel()
{
    int k = blockIdx.x * 256 + threadIdx.x;
    if (k < 512) {
        double a = -2.0 * 3.14159265358979323846 * (double)k / 1024.0;
        g_twid[k] = make_float2((float)cos(a), (float)sin(a));
    }
}

__global__ __launch_bounds__(256) void filt_kernel(const float* __restrict__ fb)
{
    __shared__ float re[1024], im[1024];
    __shared__ float2 tw[512];
    const int c = blockIdx.x, tid = threadIdx.x;
    tw[tid] = g_twid[tid]; tw[tid + 256] = g_twid[tid + 256];
    for (int i = tid; i < 1024; i += 256) {
        re[i] = (i < 512) ? fb[(size_t)(2 * c) * 512 + i] : 0.f;
        im[i] = (i < 512) ? -fb[(size_t)(2 * c + 1) * 512 + i] : 0.f;
    }
    __syncthreads();
    fft_dif(re, im, tw, tid);
    for (int i = tid; i < 1024; i += 256)
        g_P[(size_t)c * 1024 + i] = make_float2(re[i], -im[i]);
}

// ------------------------- FFT conv + |.| + pool -----------------------------
// CTA (seg, b): y[t], t in [512 seg, 512 seg + 512), all 128 channels.
// chunk h=2seg from first 256 outputs, h=2seg+1 from next 256. Exclusive writes.
__global__ __launch_bounds__(256) void conv_fft_kernel(const float* __restrict__ x)
{
    __shared__ float uRe[1024], uIm[1024], zRe[1024], zIm[1024];
    __shared__ float2 tw[512];
    __shared__ float cs0[128], cs1[128];
    __shared__ float wpart[8][4];
    const int seg = blockIdx.x, b = blockIdx.y;
    const int tid = threadIdx.x, w = tid >> 5, lane = tid & 31;

    tw[tid] = g_twid[tid]; tw[tid + 256] = g_twid[tid + 256];
    const float* xb = x + (size_t)b * NS;
    const int base = seg * 512 - 256;
    for (int i = tid; i < 1024; i += 256) {
        int g = base + i;
        uRe[i] = (g >= 0 && g < NS) ? xb[g] : 0.f;
        uIm[i] = 0.f;
    }
    if (tid < 128) { cs0[tid] = 0.f; cs1[tid] = 0.f; }
    __syncthreads();
    fft_dif(uRe, uIm, tw, tid);

    for (int p = 0; p < 64; p++) {
        const float2* P = g_P + (size_t)p * 1024;
        for (int i = tid; i < 1024; i += 256) {
            float2 pw = P[i];
            float ur = uRe[i], ui = uIm[i];
            zRe[i] = ur * pw.x - ui * pw.y;
            zIm[i] = ur * pw.y + ui * pw.x;
        }
        __syncthreads();
        ifft_dit(zRe, zIm, tw, tid);
        // thread t holds y_{2p}= Re z, y_{2p+1}= Im z at tau=t and t+256
        float v0 = fabsf(zRe[tid]),       v1 = fabsf(zIm[tid]);
        float v2 = fabsf(zRe[tid + 256]), v3 = fabsf(zIm[tid + 256]);
#pragma unroll
        for (int o = 16; o; o >>= 1) {
            v0 += __shfl_xor_sync(0xffffffffu, v0, o);
            v1 += __shfl_xor_sync(0xffffffffu, v1, o);
            v2 += __shfl_xor_sync(0xffffffffu, v2, o);
            v3 += __shfl_xor_sync(0xffffffffu, v3, o);
        }
        if (lane == 0) { wpart[w][0] = v0; wpart[w][1] = v1; wpart[w][2] = v2; wpart[w][3] = v3; }
        __syncthreads();
        if (tid < 4) {
            float s = 0.f;
#pragma unroll
            for (int ww = 0; ww < 8; ww++) s += wpart[ww][tid];
            if (tid == 0)      cs0[2 * p]     += s;
            else if (tid == 1) cs0[2 * p + 1] += s;
            else if (tid == 2) cs1[2 * p]     += s;
            else               cs1[2 * p + 1] += s;
        }
        __syncthreads();
    }
    const float scale = 1.f / (1024.f * 512.f);
    if (tid < 128) {
        g_chunk[((size_t)b * NF + 2 * seg) * DM + tid]     = cs0[tid] * scale;
        g_chunk[((size_t)b * NF + 2 * seg + 1) * DM + tid] = cs1[tid] * scale;
    }
}

// ---------------- frames + pos-encoding + embed -----------------------------
__global__ __launch_bounds__(128) void embed_kernel(const float* __restrict__ ew,
                                                    const float* __restrict__ eb)
{
    const int row = blockIdx.x;         // b*128 + t
    const int t = row & 127;
    const int tid = threadIdx.x;
    __shared__ float vec[161];
    {
        float f = g_chunk[(size_t)row * DM + tid];
        if (t > 0) f += g_chunk[(size_t)(row - 1) * DM + tid];
        vec[tid] = f;
    }
    if (tid < 33) {
        float pos = (t == 127) ? 1.0f
                               : __fadd_rn(-1.0f, __fmul_rn((float)t, __fdiv_rn(2.0f, 127.0f)));
        float v;
        if (tid == 0) v = pos;
        else {
            int k = (tid <= 16) ? (tid - 1) : (tid - 17);
            float fr = __fmul_rn(exp2f((float)k), 3.14159274101257324f);
            float prod = __fmul_rn(pos, fr);
            v = (tid <= 16) ? (float)sin((double)prod) : (float)cos((double)prod);
        }
        vec[128 + tid] = v;
    }
    __syncthreads();
    const float* w = ew + (size_t)tid * 161;
    float a0 = eb[tid], a1 = 0.f, a2 = 0.f, a3 = 0.f;
    int j = 0;
#pragma unroll 10
    for (; j + 4 <= 161; j += 4) {
        a0 = fmaf(vec[j],     w[j],     a0);
        a1 = fmaf(vec[j + 1], w[j + 1], a1);
        a2 = fmaf(vec[j + 2], w[j + 2], a2);
        a3 = fmaf(vec[j + 3], w[j + 3], a3);
    }
    for (; j < 161; j++) a0 = fmaf(vec[j], w[j], a0);
    g_h[(size_t)row * DM + tid] = (a0 + a1) + (a2 + a3);
}

// ---------------- qkv linear (K = 128, NO = 3) -------------------------------
__global__ __launch_bounds__(128) void qkv_kernel(const float* __restrict__ in,
                                                  const float* __restrict__ W,
                                                  const float* __restrict__ bias,
                                                  float* __restrict__ out)
{
    const int row0 = blockIdx.x << 3;
    const int tid = threadIdx.x;
    __shared__ __align__(16) float sv[8 * DM];
#pragma unroll
    for (int r = 0; r < 8; r++) sv[r * DM + tid] = in[(size_t)(row0 + r) * DM + tid];
    __syncthreads();
    float acc[3][8];
#pragma unroll
    for (int o = 0; o < 3; o++) {
        float bv = bias[o * DM + tid];
#pragma unroll
        for (int r = 0; r < 8; r++) acc[o][r] = bv;
    }
    const float4* sv4 = (const float4*)sv;
    const float4* W4 = (const float4*)W;
    for (int j4 = 0; j4 < 32; j4++) {
        float4 wv[3];
#pragma unroll
        for (int o = 0; o < 3; o++) wv[o] = W4[(size_t)(o * DM + tid) * 32 + j4];
#pragma unroll
        for (int r = 0; r < 8; r++) {
            float4 xv = sv4[r * 32 + j4];
#pragma unroll
            for (int o = 0; o < 3; o++) {
                acc[o][r] = fmaf(wv[o].x, xv.x, acc[o][r]);
                acc[o][r] = fmaf(wv[o].y, xv.y, acc[o][r]);
                acc[o][r] = fmaf(wv[o].z, xv.z, acc[o][r]);
                acc[o][r] = fmaf(wv[o].w, xv.w, acc[o][r]);
            }
        }
    }
#pragma unroll
    for (int r = 0; r < 8; r++)
#pragma unroll
        for (int o = 0; o < 3; o++)
            out[(size_t)(row0 + r) * 384 + o * DM + tid] = acc[o][r];
}

// ---------------- LN epilogue (rows resident in CTA) -------------------------
__device__ __forceinline__ void ln_epilogue(float v[8], const float* lnw, const float* lnb,
                                            float* h, int row0, int tid)
{
    __shared__ float red[4][8];
    const int w = tid >> 5;
    float mean[8];
#pragma unroll
    for (int r = 0; r < 8; r++) {
        float s = v[r];
#pragma unroll
        for (int o = 16; o; o >>= 1) s += __shfl_xor_sync(0xffffffffu, s, o);
        if ((tid & 31) == 0) red[w][r] = s;
    }
    __syncthreads();
#pragma unroll
    for (int r = 0; r < 8; r++)
        mean[r] = (red[0][r] + red[1][r] + red[2][r] + red[3][r]) * 0.0078125f;
    __syncthreads();
#pragma unroll
    for (int r = 0; r < 8; r++) {
        float dv = v[r] - mean[r];
        float s = dv * dv;
#pragma unroll
        for (int o = 16; o; o >>= 1) s += __shfl_xor_sync(0xffffffffu, s, o);
        if ((tid & 31) == 0) red[w][r] = s;
        v[r] = dv;
    }
    __syncthreads();
    float lw = lnw[tid], lb = lnb[tid];
#pragma unroll
    for (int r = 0; r < 8; r++) {
        float var = (red[0][r] + red[1][r] + red[2][r] + red[3][r]) * 0.0078125f;
        h[(size_t)(row0 + r) * DM + tid] = v[r] * (1.f / sqrtf(var + 1e-5f)) * lw + lb;
    }
}

// ---------------- out-proj + residual + LN -----------------------------------
__global__ __launch_bounds__(128) void proj_ln_kernel(const float* __restrict__ in,
                                                      const float* __restrict__ W,
                                                      const float* __restrict__ bias,
                                                      const float* __restrict__ lnw,
                                                      const float* __restrict__ lnb,
                                                      float* __restrict__ h)
{
    const int row0 = blockIdx.x << 3;
    const int tid = threadIdx.x;
    __shared__ __align__(16) float sv[8 * DM];
#pragma unroll
    for (int r = 0; r < 8; r++) sv[r * DM + tid] = in[(size_t)(row0 + r) * DM + tid];
    __syncthreads();
    float acc[8];
    float bv = bias[tid];
#pragma unroll
    for (int r = 0; r < 8; r++) acc[r] = bv;
    const float4* sv4 = (const float4*)sv;
    const float4* W4 = (const float4*)W;
    for (int j4 = 0; j4 < 32; j4++) {
        float4 wv = W4[(size_t)tid * 32 + j4];
#pragma unroll
        for (int r = 0; r < 8; r++) {
            float4 xv = sv4[r * 32 + j4];
            acc[r] = fmaf(wv.x, xv.x, acc[r]);
            acc[r] = fmaf(wv.y, xv.y, acc[r]);
            acc[r] = fmaf(wv.z, xv.z, acc[r]);
            acc[r] = fmaf(wv.w, xv.w, acc[r]);
        }
    }
    float v[8];
#pragma unroll
    for (int r = 0; r < 8; r++) v[r] = h[(size_t)(row0 + r) * DM + tid] + acc[r];
    ln_epilogue(v, lnw, lnb, h, row0, tid);
}

// ---------------- FFN (2 linears + relu) + residual + LN ---------------------
__global__ __launch_bounds__(128) void ffn_ln_kernel(const float* __restrict__ W1,
                                                     const float* __restrict__ b1,
                                                     const float* __restrict__ W2,
                                                     const float* __restrict__ b2,
                                                     const float* __restrict__ lnw,
                                                     const float* __restrict__ lnb,
                                                     float* __restrict__ h)
{
    const int row0 = blockIdx.x << 3;
    const int tid = threadIdx.x;
    __shared__ __align__(16) float sv[8 * DM];
    __shared__ __align__(16) float s1[8 * DM];
#pragma unroll
    for (int r = 0; r < 8; r++) sv[r * DM + tid] = h[(size_t)(row0 + r) * DM + tid];
    __syncthreads();
    float acc[8];
    {
        float bv = b1[tid];
#pragma unroll
        for (int r = 0; r < 8; r++) acc[r] = bv;
        const float4* sv4 = (const float4*)sv;
        const float4* W4 = (const float4*)W1;
        for (int j4 = 0; j4 < 32; j4++) {
            float4 wv = W4[(size_t)tid * 32 + j4];
#pragma unroll
            for (int r = 0; r < 8; r++) {
                float4 xv = sv4[r * 32 + j4];
                acc[r] = fmaf(wv.x, xv.x, acc[r]);
                acc[r] = fmaf(wv.y, xv.y, acc[r]);
                acc[r] = fmaf(wv.z, xv.z, acc[r]);
                acc[r] = fmaf(wv.w, xv.w, acc[r]);
            }
        }
    }
#pragma unroll
    for (int r = 0; r < 8; r++) s1[r * DM + tid] = fmaxf(acc[r], 0.f);
    __syncthreads();
    {
        float bv = b2[tid];
#pragma unroll
        for (int r = 0; r < 8; r++) acc[r] = bv;
        const float4* s14 = (const float4*)s1;
        const float4* W4 = (const float4*)W2;
        for (int j4 = 0; j4 < 32; j4++) {
            float4 wv = W4[(size_t)tid * 32 + j4];
#pragma unroll
            for (int r = 0; r < 8; r++) {
                float4 xv = s14[r * 32 + j4];
                acc[r] = fmaf(wv.x, xv.x, acc[r]);
                acc[r] = fmaf(wv.y, xv.y, acc[r]);
                acc[r] = fmaf(wv.z, xv.z, acc[r]);
                acc[r] = fmaf(wv.w, xv.w, acc[r]);
            }
        }
    }
    float v[8];
#pragma unroll
    for (int r = 0; r < 8; r++) v[r] = sv[r * DM + tid] + acc[r];
    ln_epilogue(v, lnw, lnb, h, row0, tid);
}

// ---------------- attention (one block per (head, batch)) -------------------
__global__ __launch_bounds__(128) void attn_kernel()
{
    const int hd = blockIdx.x, b = blockIdx.y;
    const int tid = threadIdx.x;
    __shared__ __align__(16) float ks[NF * 32];
    __shared__ __align__(16) float vs[NF * 32];
    const float* base = g_qkv + (size_t)b * NF * 384;

    for (int idx = tid; idx < NF * 32; idx += 128) {
        int j = idx >> 5, i = idx & 31;
        ks[idx] = base[j * 384 + 128 + hd * 32 + i];
        vs[idx] = base[j * 384 + 256 + hd * 32 + i];
    }
    float q[32];
    {
        const float4* qp = (const float4*)(base + (size_t)tid * 384 + hd * 32);
#pragma unroll
        for (int i = 0; i < 8; i++) {
            float4 v = qp[i];
            q[4 * i] = v.x; q[4 * i + 1] = v.y; q[4 * i + 2] = v.z; q[4 * i + 3] = v.w;
        }
    }
    __syncthreads();

    float o[32];
#pragma unroll
    for (int i = 0; i < 32; i++) o[i] = 0.f;
    float m = -FLT_MAX, l = 0.f;
    const float scale = 0.17677669529663689f;

    for (int j = 0; j < NF; j++) {
        const float4* kp = (const float4*)(ks + j * 32);
        float s = 0.f;
#pragma unroll
        for (int i = 0; i < 8; i++) {
            float4 kv = kp[i];
            s = fmaf(q[4 * i], kv.x, s); s = fmaf(q[4 * i + 1], kv.y, s);
            s = fmaf(q[4 * i + 2], kv.z, s); s = fmaf(q[4 * i + 3], kv.w, s);
        }
        s *= scale;
        float mn = fmaxf(m, s);
        float c = expf(m - mn);
        float p = expf(s - mn);
        l = l * c + p;
        const float4* vp = (const float4*)(vs + j * 32);
#pragma unroll
        for (int i = 0; i < 8; i++) {
            float4 vv = vp[i];
            o[4 * i]     = o[4 * i] * c + p * vv.x;
            o[4 * i + 1] = o[4 * i + 1] * c + p * vv.y;
            o[4 * i + 2] = o[4 * i + 2] * c + p * vv.z;
            o[4 * i + 3] = o[4 * i + 3] * c + p * vv.w;
        }
        m = mn;
    }
    float inv = 1.f / l;
    float* dst = g_attno + (size_t)(b * NF + tid) * DM + hd * 32;
#pragma unroll
    for (int i = 0; i < 32; i++) dst[i] = o[i] * inv;
}

// ---------------- attention scores + top-16 ---------------------------------
__global__ __launch_bounds__(128) void topk_kernel(const float* __restrict__ attn_w,
                                                   const float* __restrict__ attn_b)
{
    const int b = blockIdx.x, tid = threadIdx.x;
    __shared__ float sv[128];
    __shared__ float rv[128];
    __shared__ int ri[128];
    const float4* hp = (const float4*)(g_h + (size_t)(b * NF + tid) * DM);
    const float4* wp = (const float4*)attn_w;
    float s = attn_b[0];
#pragma unroll
    for (int i = 0; i < 32; i++) {
        float4 h4 = hp[i], w4 = wp[i];
        s = fmaf(h4.x, w4.x, s); s = fmaf(h4.y, w4.y, s);
        s = fmaf(h4.z, w4.z, s); s = fmaf(h4.w, w4.w, s);
    }
    sv[tid] = s;
    __syncthreads();
    for (int r = 0; r < 16; r++) {
        rv[tid] = sv[tid]; ri[tid] = tid;
        __syncthreads();
        for (int off = 64; off; off >>= 1) {
            if (tid < off) {
                float v2 = rv[tid + off]; int i2 = ri[tid + off];
                if (v2 > rv[tid] || (v2 == rv[tid] && i2 < ri[tid])) { rv[tid] = v2; ri[tid] = i2; }
            }
            __syncthreads();
        }
        if (tid == 0) {
            g_topidx[b * 16 + r] = ri[0];
            g_topval[b * 16 + r] = rv[0];
            sv[ri[0]] = -FLT_MAX;
        }
        __syncthreads();
    }
}

// ---------------- head: amp, pos/atom argmax, scatter -----------------------
__global__ __launch_bounds__(128) void scatter_kernel(const float* __restrict__ amp_w,
                                                      const float* __restrict__ amp_b,
                                                      const float* __restrict__ pos_w,
                                                      const float* __restrict__ pos_b,
                                                      const float* __restrict__ atom_w,
                                                      const float* __restrict__ atom_b,
                                                      const float* __restrict__ dmat,
                                                      float* __restrict__ out)
{
    const int rk = blockIdx.x, b = blockIdx.y, tid = threadIdx.x;
    __shared__ __align__(16) float vec[128];
    __shared__ float rv[128];
    __shared__ int ri[128];
    __shared__ float amp_s;
    __shared__ int jstar_s, astar_s;

    int id = g_topidx[b * 16 + rk];
    float val = g_topval[b * 16 + rk];
    vec[tid] = g_h[(size_t)(b * NF + id) * DM + tid] * val;
    __syncthreads();

    rv[tid] = vec[tid] * amp_w[tid];
    __syncthreads();
    for (int off = 64; off; off >>= 1) {
        if (tid < off) rv[tid] += rv[tid + off];
        __syncthreads();
    }
    if (tid == 0) amp_s = fmaxf(rv[0] + amp_b[0], 0.f);
    __syncthreads();

    const float4* vp = (const float4*)vec;

    float bv = -FLT_MAX; int bi = 1 << 30;
#pragma unroll
    for (int q = 0; q < 4; q++) {
        int o = q * 128 + tid;
        const float4* wp = (const float4*)(pos_w + (size_t)o * DM);
        float lg = pos_b[o];
#pragma unroll
        for (int i = 0; i < 32; i++) {
            float4 w4 = wp[i], v4 = vp[i];
            lg = fmaf(w4.x, v4.x, lg); lg = fmaf(w4.y, v4.y, lg);
            lg = fmaf(w4.z, v4.z, lg); lg = fmaf(w4.w, v4.w, lg);
        }
        if (lg > bv || (lg == bv && o < bi)) { bv = lg; bi = o; }
    }
    rv[tid] = bv; ri[tid] = bi;
    __syncthreads();
    for (int off = 64; off; off >>= 1) {
        if (tid < off) {
            float v2 = rv[tid + off]; int i2 = ri[tid + off];
            if (v2 > rv[tid] || (v2 == rv[tid] && i2 < ri[tid])) { rv[tid] = v2; ri[tid] = i2; }
        }
        __syncthreads();
    }
    if (tid == 0) jstar_s = ri[0];
    __syncthreads();

    bv = -FLT_MAX; bi = 1 << 30;
#pragma unroll
    for (int q = 0; q < 2; q++) {
        int o = q * 128 + tid;
        const float4* wp = (const float4*)(atom_w + (size_t)o * DM);
        float lg = atom_b[o];
#pragma unroll
        for (int i = 0; i < 32; i++) {
            float4 w4 = wp[i], v4 = vp[i];
            lg = fmaf(w4.x, v4.x, lg); lg = fmaf(w4.y, v4.y, lg);
            lg = fmaf(w4.z, v4.z, lg); lg = fmaf(w4.w, v4.w, lg);
        }
        if (lg > bv || (lg == bv && o < bi)) { bv = lg; bi = o; }
    }
    rv[tid] = bv; ri[tid] = bi;
    __syncthreads();
    for (int off = 64; off; off >>= 1) {
        if (tid < off) {
            float v2 = rv[tid + off]; int i2 = ri[tid + off];
            if (v2 > rv[tid] || (v2 == rv[tid] && i2 < ri[tid])) { rv[tid] = v2; ri[tid] = i2; }
        }
        __syncthreads();
    }
    if (tid == 0) astar_s = ri[0];
    __syncthreads();

    float amp = amp_s;
    int p = jstar_s * 64;
    int a = astar_s;
    for (int i = tid; i < 256; i += 128) {
        int t = p + i;
        if (t < NS)
            atomicAdd(out + (size_t)b * NS + t, dmat[(size_t)a * 256 + i] * amp);
    }
}

// ---------------------------------------------------------------------------
extern "C" void kernel_launch(void* const* d_in, const int* in_sizes, int n_in,
                              void* d_out, int out_size)
{
    const float* x         = (const float*)d_in[0];
    const float* fb        = (const float*)d_in[1];
    const float* embed_w   = (const float*)d_in[2];
    const float* embed_b   = (const float*)d_in[3];
    const float* in_proj_w = (const float*)d_in[4];
    const float* in_proj_b = (const float*)d_in[5];
    const float* out_w     = (const float*)d_in[6];
    const float* out_b     = (const float*)d_in[7];
    const float* lin1_w    = (const float*)d_in[8];
    const float* lin1_b    = (const float*)d_in[9];
    const float* lin2_w    = (const float*)d_in[10];
    const float* lin2_b    = (const float*)d_in[11];
    const float* ln1_w     = (const float*)d_in[12];
    const float* ln1_b     = (const float*)d_in[13];
    const float* ln2_w     = (const float*)d_in[14];
    const float* ln2_b     = (const float*)d_in[15];
    const float* attn_w    = (const float*)d_in[16];
    const float* attn_b    = (const float*)d_in[17];
    const float* amp_w     = (const float*)d_in[18];
    const float* amp_b     = (const float*)d_in[19];
    const float* pos_w     = (const float*)d_in[20];
    const float* pos_b     = (const float*)d_in[21];
    const float* atom_w    = (const float*)d_in[22];
    const float* atom_b    = (const float*)d_in[23];
    const float* dmat      = (const float*)d_in[24];
    float* out = (float*)d_out;

    float *p_h, *p_qkv, *p_attno;
    cudaGetSymbolAddress((void**)&p_h, g_h);
    cudaGetSymbolAddress((void**)&p_qkv, g_qkv);
    cudaGetSymbolAddress((void**)&p_attno, g_attno);

    twid_kernel<<<2, 256>>>();
    filt_kernel<<<64, 256>>>(fb);
    conv_fft_kernel<<<dim3(64, NB), 256>>>(x);

    embed_kernel<<<NB * NF, 128>>>(embed_w, embed_b);

    for (int i = 0; i < 6; i++) {
        qkv_kernel<<<512, 128>>>(p_h, in_proj_w + (size_t)i * 384 * 128,
                                 in_proj_b + i * 384, p_qkv);
        attn_kernel<<<dim3(4, NB), 128>>>();
        proj_ln_kernel<<<512, 128>>>(p_attno, out_w + (size_t)i * 128 * 128,
                                     out_b + i * 128, ln1_w + i * 128, ln1_b + i * 128, p_h);
        ffn_ln_kernel<<<512, 128>>>(lin1_w + (size_t)i * 128 * 128, lin1_b + i * 128,
                                    lin2_w + (size_t)i * 128 * 128, lin2_b + i * 128,
                                    ln2_w + i * 128, ln2_b + i * 128, p_h);
    }

    topk_kernel<<<NB, 128>>>(attn_w, attn_b);
    cudaMemsetAsync(d_out, 0, (size_t)out_size * sizeof(float), 0);
    scatter_kernel<<<dim3(16, NB), 128>>>(amp_w, amp_b, pos_w, pos_b,
                                          atom_w, atom_b, dmat, out);
}

// round 8
// speedup vs baseline: 1.6019x; 1.1223x over previous
#include <cuda_runtime.h>
#include <math.h>
#include <float.h>

#define NB 32
#define NS 32768
#define NF 128
#define DM 128

// ------------------------- scratch (device globals) -------------------------
__device__ float2 g_twid[512];            // exp(-2*pi*i*k/1024)
__device__ float2 g_P[64 * 1024];         // conj(FFT(w_2c - i w_2c+1)), scrambled
__device__ float g_ewT[161 * 128];        // transposed embed weights
__device__ float g_chunk[NB * NF * DM];
__device__ float g_h[NB * NF * DM];
__device__ float g_qkv[NB * NF * 384];
__device__ float g_attno[NB * NF * DM];
__device__ int   g_topidx[NB * 16];
__device__ float g_topval[NB * 16];

// ------------------------- butterflies ---------------------------------------
__device__ __forceinline__ void bf_dif(float& ar, float& ai, float& br, float& bi, float2 w)
{
    float xr = ar - br, xi = ai - bi;
    ar += br; ai += bi;
    br = xr * w.x - xi * w.y;
    bi = xr * w.y + xi * w.x;
}
__device__ __forceinline__ void bf_dit(float& ar, float& ai, float& br, float& bi, float2 w)
{
    // applies conj(w) to b, then sum/diff
    float tr = br * w.x + bi * w.y;
    float ti = bi * w.x - br * w.y;
    br = ar - tr; bi = ai - ti;
    ar += tr; ai += ti;
}

// ------------------------- forward 1024-pt DIF (in-place, natural->bitrev) ---
// 256 threads. smem re/im must be 16B aligned. Caller syncs before entry.
__device__ __forceinline__ void fft1024_dif(float* re, float* im, const float2* tw, int tid)
{
    {   // stages h=512, 256   (lane-consecutive: conflict-free)
        int r = tid;
        float ar = re[r],       ai = im[r];
        float br = re[r + 256], bi = im[r + 256];
        float cr = re[r + 512], ci = im[r + 512];
        float dr = re[r + 768], di = im[r + 768];
        bf_dif(ar, ai, cr, ci, tw[r]);
        bf_dif(br, bi, dr, di, tw[r + 256]);
        float2 v = tw[2 * r];
        bf_dif(ar, ai, br, bi, v);
        bf_dif(cr, ci, dr, di, v);
        re[r] = ar;       im[r] = ai;
        re[r + 256] = br; im[r + 256] = bi;
        re[r + 512] = cr; im[r + 512] = ci;
        re[r + 768] = dr; im[r + 768] = di;
    }
    __syncthreads();
    {   // stages h=128, 64
        int q = tid >> 6, r = tid & 63, i0 = q * 256 + r;
        float ar = re[i0],       ai = im[i0];
        float br = re[i0 + 64],  bi = im[i0 + 64];
        float cr = re[i0 + 128], ci = im[i0 + 128];
        float dr = re[i0 + 192], di = im[i0 + 192];
        bf_dif(ar, ai, cr, ci, tw[4 * r]);
        bf_dif(br, bi, dr, di, tw[4 * r + 256]);
        float2 v = tw[8 * r];
        bf_dif(ar, ai, br, bi, v);
        bf_dif(cr, ci, dr, di, v);
        re[i0] = ar;       im[i0] = ai;
        re[i0 + 64] = br;  im[i0 + 64] = bi;
        re[i0 + 128] = cr; im[i0 + 128] = ci;
        re[i0 + 192] = dr; im[i0 + 192] = di;
    }
    __syncthreads();
    {   // stages h=32,16,8,4 (shuffle), 2,1 (in-thread); thread t holds 4t..4t+3
        float4 R = ((const float4*)re)[tid];
        float4 I = ((const float4*)im)[tid];
        float vr[4] = {R.x, R.y, R.z, R.w};
        float vi[4] = {I.x, I.y, I.z, I.w};
#pragma unroll
        for (int s = 3; s >= 0; s--) {
            const int mask = 1 << s;
            const int step = 128 >> s;                 // 512/h, h = 4*mask
            const int kb = 4 * (tid & (mask - 1));
            const bool up = (tid & mask) != 0;
#pragma unroll
            for (int j = 0; j < 4; j++) {
                float orr = __shfl_xor_sync(0xffffffffu, vr[j], mask);
                float oii = __shfl_xor_sync(0xffffffffu, vi[j], mask);
                float2 w = tw[(kb + j) * step];
                float sr = vr[j] + orr, si = vi[j] + oii;
                float dr = orr - vr[j], di = oii - vi[j];
                float pr = dr * w.x - di * w.y;
                float pi = dr * w.y + di * w.x;
                vr[j] = up ? pr : sr;
                vi[j] = up ? pi : si;
            }
        }
        {   // h=2: pairs (0,2) W=1; (1,3) W=tw[256]=(0,-1)
            float s0r = vr[0] + vr[2], s0i = vi[0] + vi[2];
            float d0r = vr[0] - vr[2], d0i = vi[0] - vi[2];
            vr[0] = s0r; vi[0] = s0i; vr[2] = d0r; vi[2] = d0i;
            float s1r = vr[1] + vr[3], s1i = vi[1] + vi[3];
            float d1r = vr[1] - vr[3], d1i = vi[1] - vi[3];
            vr[1] = s1r; vi[1] = s1i;
            vr[3] = d1i; vi[3] = -d1r;                 // *(0,-1)
        }
        {   // h=1: W=1
            float t0r = vr[0] + vr[1], t0i = vi[0] + vi[1];
            float t1r = vr[0] - vr[1], t1i = vi[0] - vi[1];
            float t2r = vr[2] + vr[3], t2i = vi[2] + vi[3];
            float t3r = vr[2] - vr[3], t3i = vi[2] - vi[3];
            vr[0] = t0r; vi[0] = t0i; vr[1] = t1r; vi[1] = t1i;
            vr[2] = t2r; vi[2] = t2i; vr[3] = t3r; vi[3] = t3i;
        }
        ((float4*)re)[tid] = make_float4(vr[0], vr[1], vr[2], vr[3]);
        ((float4*)im)[tid] = make_float4(vi[0], vi[1], vi[2], vi[3]);
    }
    __syncthreads();
}

// ------------------------- precompute kernels --------------------------------
__global__ void twid_kernel()
{
    int k = blockIdx.x * 256 + threadIdx.x;
    if (k < 512) {
        double a = -2.0 * 3.14159265358979323846 * (double)k / 1024.0;
        g_twid[k] = make_float2((float)cos(a), (float)sin(a));
    }
}

__global__ __launch_bounds__(256) void filt_kernel(const float* __restrict__ fb)
{
    __shared__ __align__(16) float re[1024], im[1024];
    __shared__ __align__(16) float2 tw[512];
    const int c = blockIdx.x, tid = threadIdx.x;
    tw[tid] = g_twid[tid]; tw[tid + 256] = g_twid[tid + 256];
    for (int i = tid; i < 1024; i += 256) {
        re[i] = (i < 512) ? fb[(size_t)(2 * c) * 512 + i] : 0.f;
        im[i] = (i < 512) ? -fb[(size_t)(2 * c + 1) * 512 + i] : 0.f;
    }
    __syncthreads();
    fft1024_dif(re, im, tw, tid);
    for (int i = tid; i < 1024; i += 256)
        g_P[(size_t)c * 1024 + i] = make_float2(re[i], -im[i]);
}

__global__ void ewt_kernel(const float* __restrict__ ew)
{
    int i = blockIdx.x * 256 + threadIdx.x;
    if (i < 161 * 128) {
        int j = i >> 7, c = i & 127;
        g_ewT[j * 128 + c] = ew[(size_t)c * 161 + j];
    }
}

// ------------------------- FFT conv + |.| + pool -----------------------------
// CTA (seg, b): y[t], t in [512 seg, 512 seg + 512), all 128 channels.
__global__ __launch_bounds__(256) void conv_fft_kernel(const float* __restrict__ x)
{
    __shared__ __align__(16) float uRe[1024], uIm[1024], zRe[1024], zIm[1024];
    __shared__ __align__(16) float2 tw[512];
    __shared__ float cs0[128], cs1[128];
    __shared__ float wpart[8][4];
    const int seg = blockIdx.x, b = blockIdx.y;
    const int tid = threadIdx.x, w = tid >> 5, lane = tid & 31;

    tw[tid] = g_twid[tid]; tw[tid + 256] = g_twid[tid + 256];
    const float* xb = x + (size_t)b * NS;
    const int base = seg * 512 - 256;
    for (int i = tid; i < 1024; i += 256) {
        int g = base + i;
        uRe[i] = (g >= 0 && g < NS) ? xb[g] : 0.f;
        uIm[i] = 0.f;
    }
    if (tid < 128) { cs0[tid] = 0.f; cs1[tid] = 0.f; }
    __syncthreads();
    fft1024_dif(uRe, uIm, tw, tid);

    for (int p = 0; p < 64; p++) {
        const float4* Pp = (const float4*)(g_P + (size_t)p * 1024);
        // ---- trip A: fused pointwise + DIT stages 1,2 (in-thread), 4..64 (shuffle)
        {
            float4 UR = ((const float4*)uRe)[tid];
            float4 UI = ((const float4*)uIm)[tid];
            float4 P0 = Pp[2 * tid], P1 = Pp[2 * tid + 1];
            float vr[4], vi[4];
            vr[0] = UR.x * P0.x - UI.x * P0.y; vi[0] = UR.x * P0.y + UI.x * P0.x;
            vr[1] = UR.y * P0.z - UI.y * P0.w; vi[1] = UR.y * P0.w + UI.y * P0.z;
            vr[2] = UR.z * P1.x - UI.z * P1.y; vi[2] = UR.z * P1.y + UI.z * P1.x;
            vr[3] = UR.w * P1.z - UI.w * P1.w; vi[3] = UR.w * P1.w + UI.w * P1.z;
            {   // h=1 (Wc=1)
                float t0r = vr[0] + vr[1], t0i = vi[0] + vi[1];
                float t1r = vr[0] - vr[1], t1i = vi[0] - vi[1];
                float t2r = vr[2] + vr[3], t2i = vi[2] + vi[3];
                float t3r = vr[2] - vr[3], t3i = vi[2] - vi[3];
                vr[0] = t0r; vi[0] = t0i; vr[1] = t1r; vi[1] = t1i;
                vr[2] = t2r; vi[2] = t2i; vr[3] = t3r; vi[3] = t3i;
            }
            {   // h=2: (0,2) Wc=1; (1,3) Wc=conj(0,-1)=(0,1): tv = (-vi3, vr3)
                float s0r = vr[0] + vr[2], s0i = vi[0] + vi[2];
                float d0r = vr[0] - vr[2], d0i = vi[0] - vi[2];
                vr[0] = s0r; vi[0] = s0i; vr[2] = d0r; vi[2] = d0i;
                float tr = -vi[3], ti = vr[3];
                float nr = vr[1] + tr, ni = vi[1] + ti;
                float mr = vr[1] - tr, mi = vi[1] - ti;
                vr[1] = nr; vi[1] = ni; vr[3] = mr; vi[3] = mi;
            }
#pragma unroll
            for (int s = 0; s < 5; s++) {               // h = 4,8,16,32,64
                const int mask = 1 << s;
                const int step = 128 >> s;              // 512/h
                const int kb = 4 * (tid & (mask - 1));
                const bool up = (tid & mask) != 0;
#pragma unroll
                for (int j = 0; j < 4; j++) {
                    float orr = __shfl_xor_sync(0xffffffffu, vr[j], mask);
                    float oii = __shfl_xor_sync(0xffffffffu, vi[j], mask);
                    float2 tww = tw[(kb + j) * step];
                    float sr = up ? vr[j] : orr;        // value of x[i+h]
                    float sI = up ? vi[j] : oii;
                    float tr = sr * tww.x + sI * tww.y; // * conj(w)
                    float ti = sI * tww.x - sr * tww.y;
                    float lr = vr[j] + tr, li = vi[j] + ti;   // lower result
                    float ur_ = orr - tr, ui_ = oii - ti;     // upper result
                    vr[j] = up ? ur_ : lr;
                    vi[j] = up ? ui_ : li;
                }
            }
            ((float4*)zRe)[tid] = make_float4(vr[0], vr[1], vr[2], vr[3]);
            ((float4*)zIm)[tid] = make_float4(vi[0], vi[1], vi[2], vi[3]);
        }
        __syncthreads();
        // ---- trip B: DIT stages h=128, 256
        {
            int q = tid >> 7, r = tid & 127, i0 = q * 512 + r;
            float ar = zRe[i0],       ai = zIm[i0];
            float br = zRe[i0 + 128], bi = zIm[i0 + 128];
            float cr = zRe[i0 + 256], ci = zIm[i0 + 256];
            float dr = zRe[i0 + 384], di = zIm[i0 + 384];
            float2 w1 = tw[4 * r];
            bf_dit(ar, ai, br, bi, w1);
            bf_dit(cr, ci, dr, di, w1);
            bf_dit(ar, ai, cr, ci, tw[2 * r]);
            bf_dit(br, bi, dr, di, tw[2 * r + 256]);
            zRe[i0] = ar;       zIm[i0] = ai;
            zRe[i0 + 128] = br; zIm[i0 + 128] = bi;
            zRe[i0 + 256] = cr; zIm[i0 + 256] = ci;
            zRe[i0 + 384] = dr; zIm[i0 + 384] = di;
        }
        __syncthreads();
        // ---- trip C: stage h=512 (only needed halves) + pooling
        float v0, v1, v2, v3;
        {
            float ar = zRe[tid], ai = zIm[tid];
            float cr = zRe[tid + 512], ci = zIm[tid + 512];
            float2 w1 = tw[tid];
            float tr = cr * w1.x + ci * w1.y, ti = ci * w1.x - cr * w1.y;
            float y0r = ar + tr, y0i = ai + ti;
            float br = zRe[tid + 256], bi = zIm[tid + 256];
            float dr = zRe[tid + 768], di = zIm[tid + 768];
            float2 w2 = tw[tid + 256];
            tr = dr * w2.x + di * w2.y; ti = di * w2.x - dr * w2.y;
            float y1r = br + tr, y1i = bi + ti;
            v0 = fabsf(y0r); v1 = fabsf(y0i);
            v2 = fabsf(y1r); v3 = fabsf(y1i);
        }
#pragma unroll
        for (int o = 16; o; o >>= 1) {
            v0 += __shfl_xor_sync(0xffffffffu, v0, o);
            v1 += __shfl_xor_sync(0xffffffffu, v1, o);
            v2 += __shfl_xor_sync(0xffffffffu, v2, o);
            v3 += __shfl_xor_sync(0xffffffffu, v3, o);
        }
        if (lane == 0) { wpart[w][0] = v0; wpart[w][1] = v1; wpart[w][2] = v2; wpart[w][3] = v3; }
        __syncthreads();
        if (tid < 4) {
            float s = 0.f;
#pragma unroll
            for (int ww = 0; ww < 8; ww++) s += wpart[ww][tid];
            if (tid == 0)      cs0[2 * p]     += s;
            else if (tid == 1) cs0[2 * p + 1] += s;
            else if (tid == 2) cs1[2 * p]     += s;
            else               cs1[2 * p + 1] += s;
        }
        __syncthreads();
    }
    const float scale = 1.f / (1024.f * 512.f);
    if (tid < 128) {
        g_chunk[((size_t)b * NF + 2 * seg) * DM + tid]     = cs0[tid] * scale;
        g_chunk[((size_t)b * NF + 2 * seg + 1) * DM + tid] = cs1[tid] * scale;
    }
}

// ---------------- frames + pos-encoding + embed -----------------------------
__global__ __launch_bounds__(128) void embed_kernel(const float* __restrict__ eb)
{
    const int row = blockIdx.x;         // b*128 + t
    const int t = row & 127;
    const int tid = threadIdx.x;
    __shared__ float vec[161];
    {
        float f = g_chunk[(size_t)row * DM + tid];
        if (t > 0) f += g_chunk[(size_t)(row - 1) * DM + tid];
        vec[tid] = f;
    }
    if (tid < 33) {
        float pos = (t == 127) ? 1.0f
                               : __fadd_rn(-1.0f, __fmul_rn((float)t, __fdiv_rn(2.0f, 127.0f)));
        float v;
        if (tid == 0) v = pos;
        else {
            int k = (tid <= 16) ? (tid - 1) : (tid - 17);
            float fr = __fmul_rn(exp2f((float)k), 3.14159274101257324f);
            float prod = __fmul_rn(pos, fr);
            v = (tid <= 16) ? (float)sin((double)prod) : (float)cos((double)prod);
        }
        vec[128 + tid] = v;
    }
    __syncthreads();
    float a0 = eb[tid], a1 = 0.f, a2 = 0.f, a3 = 0.f;
    int j = 0;
#pragma unroll 10
    for (; j + 4 <= 161; j += 4) {
        a0 = fmaf(vec[j],     g_ewT[(j)     * 128 + tid], a0);
        a1 = fmaf(vec[j + 1], g_ewT[(j + 1) * 128 + tid], a1);
        a2 = fmaf(vec[j + 2], g_ewT[(j + 2) * 128 + tid], a2);
        a3 = fmaf(vec[j + 3], g_ewT[(j + 3) * 128 + tid], a3);
    }
    for (; j < 161; j++) a0 = fmaf(vec[j], g_ewT[j * 128 + tid], a0);
    g_h[(size_t)row * DM + tid] = (a0 + a1) + (a2 + a3);
}

// ---------------- qkv linear (K = 128, NO = 3) -------------------------------
__global__ __launch_bounds__(128) void qkv_kernel(const float* __restrict__ in,
                                                  const float* __restrict__ W,
                                                  const float* __restrict__ bias,
                                                  float* __restrict__ out)
{
    const int row0 = blockIdx.x << 3;
    const int tid = threadIdx.x;
    __shared__ __align__(16) float sv[8 * DM];
#pragma unroll
    for (int r = 0; r < 8; r++) sv[r * DM + tid] = in[(size_t)(row0 + r) * DM + tid];
    __syncthreads();
    float acc[3][8];
#pragma unroll
    for (int o = 0; o < 3; o++) {
        float bv = bias[o * DM + tid];
#pragma unroll
        for (int r = 0; r < 8; r++) acc[o][r] = bv;
    }
    const float4* sv4 = (const float4*)sv;
    const float4* W4 = (const float4*)W;
    for (int j4 = 0; j4 < 32; j4++) {
        float4 wv[3];
#pragma unroll
        for (int o = 0; o < 3; o++) wv[o] = W4[(size_t)(o * DM + tid) * 32 + j4];
#pragma unroll
        for (int r = 0; r < 8; r++) {
            float4 xv = sv4[r * 32 + j4];
#pragma unroll
            for (int o = 0; o < 3; o++) {
                acc[o][r] = fmaf(wv[o].x, xv.x, acc[o][r]);
                acc[o][r] = fmaf(wv[o].y, xv.y, acc[o][r]);
                acc[o][r] = fmaf(wv[o].z, xv.z, acc[o][r]);
                acc[o][r] = fmaf(wv[o].w, xv.w, acc[o][r]);
            }
        }
    }
#pragma unroll
    for (int r = 0; r < 8; r++)
#pragma unroll
        for (int o = 0; o < 3; o++)
            out[(size_t)(row0 + r) * 384 + o * DM + tid] = acc[o][r];
}

// ---------------- LN epilogue (rows resident in CTA) -------------------------
__device__ __forceinline__ void ln_epilogue(float v[8], const float* lnw, const float* lnb,
                                            float* h, int row0, int tid)
{
    __shared__ float red[4][8];
    const int w = tid >> 5;
    float mean[8];
#pragma unroll
    for (int r = 0; r < 8; r++) {
        float s = v[r];
#pragma unroll
        for (int o = 16; o; o >>= 1) s += __shfl_xor_sync(0xffffffffu, s, o);
        if ((tid & 31) == 0) red[w][r] = s;
    }
    __syncthreads();
#pragma unroll
    for (int r = 0; r < 8; r++)
        mean[r] = (red[0][r] + red[1][r] + red[2][r] + red[3][r]) * 0.0078125f;
    __syncthreads();
#pragma unroll
    for (int r = 0; r < 8; r++) {
        float dv = v[r] - mean[r];
        float s = dv * dv;
#pragma unroll
        for (int o = 16; o; o >>= 1) s += __shfl_xor_sync(0xffffffffu, s, o);
        if ((tid & 31) == 0) red[w][r] = s;
        v[r] = dv;
    }
    __syncthreads();
    float lw = lnw[tid], lb = lnb[tid];
#pragma unroll
    for (int r = 0; r < 8; r++) {
        float var = (red[0][r] + red[1][r] + red[2][r] + red[3][r]) * 0.0078125f;
        h[(size_t)(row0 + r) * DM + tid] = v[r] * (1.f / sqrtf(var + 1e-5f)) * lw + lb;
    }
}

// ---------------- out-proj + residual + LN -----------------------------------
__global__ __launch_bounds__(128) void proj_ln_kernel(const float* __restrict__ in,
                                                      const float* __restrict__ W,
                                                      const float* __restrict__ bias,
                                                      const float* __restrict__ lnw,
                                                      const float* __restrict__ lnb,
                                                      float* __restrict__ h)
{
    const int row0 = blockIdx.x << 3;
    const int tid = threadIdx.x;
    __shared__ __align__(16) float sv[8 * DM];
#pragma unroll
    for (int r = 0; r < 8; r++) sv[r * DM + tid] = in[(size_t)(row0 + r) * DM + tid];
    __syncthreads();
    float acc[8];
    float bv = bias[tid];
#pragma unroll
    for (int r = 0; r < 8; r++) acc[r] = bv;
    const float4* sv4 = (const float4*)sv;
    const float4* W4 = (const float4*)W;
    for (int j4 = 0; j4 < 32; j4++) {
        float4 wv = W4[(size_t)tid * 32 + j4];
#pragma unroll
        for (int r = 0; r < 8; r++) {
            float4 xv = sv4[r * 32 + j4];
            acc[r] = fmaf(wv.x, xv.x, acc[r]);
            acc[r] = fmaf(wv.y, xv.y, acc[r]);
            acc[r] = fmaf(wv.z, xv.z, acc[r]);
            acc[r] = fmaf(wv.w, xv.w, acc[r]);
        }
    }
    float v[8];
#pragma unroll
    for (int r = 0; r < 8; r++) v[r] = h[(size_t)(row0 + r) * DM + tid] + acc[r];
    ln_epilogue(v, lnw, lnb, h, row0, tid);
}

// ---------------- FFN (2 linears + relu) + residual + LN ---------------------
__global__ __launch_bounds__(128) void ffn_ln_kernel(const float* __restrict__ W1,
                                                     const float* __restrict__ b1,
                                                     const float* __restrict__ W2,
                                                     const float* __restrict__ b2,
                                                     const float* __restrict__ lnw,
                                                     const float* __restrict__ lnb,
                                                     float* __restrict__ h)
{
    const int row0 = blockIdx.x << 3;
    const int tid = threadIdx.x;
    __shared__ __align__(16) float sv[8 * DM];
    __shared__ __align__(16) float s1[8 * DM];
#pragma unroll
    for (int r = 0; r < 8; r++) sv[r * DM + tid] = h[(size_t)(row0 + r) * DM + tid];
    __syncthreads();
    float acc[8];
    {
        float bv = b1[tid];
#pragma unroll
        for (int r = 0; r < 8; r++) acc[r] = bv;
        const float4* sv4 = (const float4*)sv;
        const float4* W4 = (const float4*)W1;
        for (int j4 = 0; j4 < 32; j4++) {
            float4 wv = W4[(size_t)tid * 32 + j4];
#pragma unroll
            for (int r = 0; r < 8; r++) {
                float4 xv = sv4[r * 32 + j4];
                acc[r] = fmaf(wv.x, xv.x, acc[r]);
                acc[r] = fmaf(wv.y, xv.y, acc[r]);
                acc[r] = fmaf(wv.z, xv.z, acc[r]);
                acc[r] = fmaf(wv.w, xv.w, acc[r]);
            }
        }
    }
#pragma unroll
    for (int r = 0; r < 8; r++) s1[r * DM + tid] = fmaxf(acc[r], 0.f);
    __syncthreads();
    {
        float bv = b2[tid];
#pragma unroll
        for (int r = 0; r < 8; r++) acc[r] = bv;
        const float4* s14 = (const float4*)s1;
        const float4* W4 = (const float4*)W2;
        for (int j4 = 0; j4 < 32; j4++) {
            float4 wv = W4[(size_t)tid * 32 + j4];
#pragma unroll
            for (int r = 0; r < 8; r++) {
                float4 xv = s14[r * 32 + j4];
                acc[r] = fmaf(wv.x, xv.x, acc[r]);
                acc[r] = fmaf(wv.y, xv.y, acc[r]);
                acc[r] = fmaf(wv.z, xv.z, acc[r]);
                acc[r] = fmaf(wv.w, xv.w, acc[r]);
            }
        }
    }
    float v[8];
#pragma unroll
    for (int r = 0; r < 8; r++) v[r] = sv[r * DM + tid] + acc[r];
    ln_epilogue(v, lnw, lnb, h, row0, tid);
}

// ---------------- attention (one block per (head, batch)) -------------------
__global__ __launch_bounds__(128) void attn_kernel()
{
    const int hd = blockIdx.x, b = blockIdx.y;
    const int tid = threadIdx.x;
    __shared__ __align__(16) float ks[NF * 32];
    __shared__ __align__(16) float vs[NF * 32];
    const float* base = g_qkv + (size_t)b * NF * 384;

    for (int idx = tid; idx < NF * 32; idx += 128) {
        int j = idx >> 5, i = idx & 31;
        ks[idx] = base[j * 384 + 128 + hd * 32 + i];
        vs[idx] = base[j * 384 + 256 + hd * 32 + i];
    }
    float q[32];
    {
        const float4* qp = (const float4*)(base + (size_t)tid * 384 + hd * 32);
#pragma unroll
        for (int i = 0; i < 8; i++) {
            float4 v = qp[i];
            q[4 * i] = v.x; q[4 * i + 1] = v.y; q[4 * i + 2] = v.z; q[4 * i + 3] = v.w;
        }
    }
    __syncthreads();

    float o[32];
#pragma unroll
    for (int i = 0; i < 32; i++) o[i] = 0.f;
    float m = -FLT_MAX, l = 0.f;
    const float scale = 0.17677669529663689f;

    for (int j = 0; j < NF; j++) {
        const float4* kp = (const float4*)(ks + j * 32);
        float s = 0.f;
#pragma unroll
        for (int i = 0; i < 8; i++) {
            float4 kv = kp[i];
            s = fmaf(q[4 * i], kv.x, s); s = fmaf(q[4 * i + 1], kv.y, s);
            s = fmaf(q[4 * i + 2], kv.z, s); s = fmaf(q[4 * i + 3], kv.w, s);
        }
        s *= scale;
        float mn = fmaxf(m, s);
        float c = expf(m - mn);
        float p = expf(s - mn);
        l = l * c + p;
        const float4* vp = (const float4*)(vs + j * 32);
#pragma unroll
        for (int i = 0; i < 8; i++) {
            float4 vv = vp[i];
            o[4 * i]     = o[4 * i] * c + p * vv.x;
            o[4 * i + 1] = o[4 * i + 1] * c + p * vv.y;
            o[4 * i + 2] = o[4 * i + 2] * c + p * vv.z;
            o[4 * i + 3] = o[4 * i + 3] * c + p * vv.w;
        }
        m = mn;
    }
    float inv = 1.f / l;
    float* dst = g_attno + (size_t)(b * NF + tid) * DM + hd * 32;
#pragma unroll
    for (int i = 0; i < 32; i++) dst[i] = o[i] * inv;
}

// ---------------- attention scores + top-16 ---------------------------------
__global__ __launch_bounds__(128) void topk_kernel(const float* __restrict__ attn_w,
                                                   const float* __restrict__ attn_b)
{
    const int b = blockIdx.x, tid = threadIdx.x;
    __shared__ float sv[128];
    __shared__ float rv[128];
    __shared__ int ri[128];
    const float4* hp = (const float4*)(g_h + (size_t)(b * NF + tid) * DM);
    const float4* wp = (const float4*)attn_w;
    float s = attn_b[0];
#pragma unroll
    for (int i = 0; i < 32; i++) {
        float4 h4 = hp[i], w4 = wp[i];
        s = fmaf(h4.x, w4.x, s); s = fmaf(h4.y, w4.y, s);
        s = fmaf(h4.z, w4.z, s); s = fmaf(h4.w, w4.w, s);
    }
    sv[tid] = s;
    __syncthreads();
    for (int r = 0; r < 16; r++) {
        rv[tid] = sv[tid]; ri[tid] = tid;
        __syncthreads();
        for (int off = 64; off; off >>= 1) {
            if (tid < off) {
                float v2 = rv[tid + off]; int i2 = ri[tid + off];
                if (v2 > rv[tid] || (v2 == rv[tid] && i2 < ri[tid])) { rv[tid] = v2; ri[tid] = i2; }
            }
            __syncthreads();
        }
        if (tid == 0) {
            g_topidx[b * 16 + r] = ri[0];
            g_topval[b * 16 + r] = rv[0];
            sv[ri[0]] = -FLT_MAX;
        }
        __syncthreads();
    }
}

// ---------------- head: amp, pos/atom argmax, scatter -----------------------
__global__ __launch_bounds__(128) void scatter_kernel(const float* __restrict__ amp_w,
                                                      const float* __restrict__ amp_b,
                                                      const float* __restrict__ pos_w,
                                                      const float* __restrict__ pos_b,
                                                      const float* __restrict__ atom_w,
                                                      const float* __restrict__ atom_b,
                                                      const float* __restrict__ dmat,
                                                      float* __restrict__ out)
{
    const int rk = blockIdx.x, b = blockIdx.y, tid = threadIdx.x;
    __shared__ __align__(16) float vec[128];
    __shared__ float rv[128];
    __shared__ int ri[128];
    __shared__ float amp_s;
    __shared__ int jstar_s, astar_s;

    int id = g_topidx[b * 16 + rk];
    float val = g_topval[b * 16 + rk];
    vec[tid] = g_h[(size_t)(b * NF + id) * DM + tid] * val;
    __syncthreads();

    rv[tid] = vec[tid] * amp_w[tid];
    __syncthreads();
    for (int off = 64; off; off >>= 1) {
        if (tid < off) rv[tid] += rv[tid + off];
        __syncthreads();
    }
    if (tid == 0) amp_s = fmaxf(rv[0] + amp_b[0], 0.f);
    __syncthreads();

    const float4* vp = (const float4*)vec;

    float bv = -FLT_MAX; int bi = 1 << 30;
#pragma unroll
    for (int q = 0; q < 4; q++) {
        int o = q * 128 + tid;
        const float4* wp = (const float4*)(pos_w + (size_t)o * DM);
        float lg = pos_b[o];
#pragma unroll
        for (int i = 0; i < 32; i++) {
            float4 w4 = wp[i], v4 = vp[i];
            lg = fmaf(w4.x, v4.x, lg); lg = fmaf(w4.y, v4.y, lg);
            lg = fmaf(w4.z, v4.z, lg); lg = fmaf(w4.w, v4.w, lg);
        }
        if (lg > bv || (lg == bv && o < bi)) { bv = lg; bi = o; }
    }
    rv[tid] = bv; ri[tid] = bi;
    __syncthreads();
    for (int off = 64; off; off >>= 1) {
        if (tid < off) {
            float v2 = rv[tid + off]; int i2 = ri[tid + off];
            if (v2 > rv[tid] || (v2 == rv[tid] && i2 < ri[tid])) { rv[tid] = v2; ri[tid] = i2; }
        }
        __syncthreads();
    }
    if (tid == 0) jstar_s = ri[0];
    __syncthreads();

    bv = -FLT_MAX; bi = 1 << 30;
#pragma unroll
    for (int q = 0; q < 2; q++) {
        int o = q * 128 + tid;
        const float4* wp = (const float4*)(atom_w + (size_t)o * DM);
        float lg = atom_b[o];
#pragma unroll
        for (int i = 0; i < 32; i++) {
            float4 w4 = wp[i], v4 = vp[i];
            lg = fmaf(w4.x, v4.x, lg); lg = fmaf(w4.y, v4.y, lg);
            lg = fmaf(w4.z, v4.z, lg); lg = fmaf(w4.w, v4.w, lg);
        }
        if (lg > bv || (lg == bv && o < bi)) { bv = lg; bi = o; }
    }
    rv[tid] = bv; ri[tid] = bi;
    __syncthreads();
    for (int off = 64; off; off >>= 1) {
        if (tid < off) {
            float v2 = rv[tid + off]; int i2 = ri[tid + off];
            if (v2 > rv[tid] || (v2 == rv[tid] && i2 < ri[tid])) { rv[tid] = v2; ri[tid] = i2; }
        }
        __syncthreads();
    }
    if (tid == 0) astar_s = ri[0];
    __syncthreads();

    float amp = amp_s;
    int p = jstar_s * 64;
    int a = astar_s;
    for (int i = tid; i < 256; i += 128) {
        int t = p + i;
        if (t < NS)
            atomicAdd(out + (size_t)b * NS + t, dmat[(size_t)a * 256 + i] * amp);
    }
}

// ---------------------------------------------------------------------------
extern "C" void kernel_launch(void* const* d_in, const int* in_sizes, int n_in,
                              void* d_out, int out_size)
{
    const float* x         = (const float*)d_in[0];
    const float* fb        = (const float*)d_in[1];
    const float* embed_w   = (const float*)d_in[2];
    const float* embed_b   = (const float*)d_in[3];
    const float* in_proj_w = (const float*)d_in[4];
    const float* in_proj_b = (const float*)d_in[5];
    const float* out_w     = (const float*)d_in[6];
    const float* out_b     = (const float*)d_in[7];
    const float* lin1_w    = (const float*)d_in[8];
    const float* lin1_b    = (const float*)d_in[9];
    const float* lin2_w    = (const float*)d_in[10];
    const float* lin2_b    = (const float*)d_in[11];
    const float* ln1_w     = (const float*)d_in[12];
    const float* ln1_b     = (const float*)d_in[13];
    const float* ln2_w     = (const float*)d_in[14];
    const float* ln2_b     = (const float*)d_in[15];
    const float* attn_w    = (const float*)d_in[16];
    const float* attn_b    = (const float*)d_in[17];
    const float* amp_w     = (const float*)d_in[18];
    const float* amp_b     = (const float*)d_in[19];
    const float* pos_w     = (const float*)d_in[20];
    const float* pos_b     = (const float*)d_in[21];
    const float* atom_w    = (const float*)d_in[22];
    const float* atom_b    = (const float*)d_in[23];
    const float* dmat      = (const float*)d_in[24];
    float* out = (float*)d_out;

    float *p_h, *p_qkv, *p_attno;
    cudaGetSymbolAddress((void**)&p_h, g_h);
    cudaGetSymbolAddress((void**)&p_qkv, g_qkv);
    cudaGetSymbolAddress((void**)&p_attno, g_attno);

    twid_kernel<<<2, 256>>>();
    ewt_kernel<<<(161 * 128 + 255) / 256, 256>>>(embed_w);
    filt_kernel<<<64, 256>>>(fb);
    conv_fft_kernel<<<dim3(64, NB), 256>>>(x);

    embed_kernel<<<NB * NF, 128>>>(embed_b);

    for (int i = 0; i < 6; i++) {
        qkv_kernel<<<512, 128>>>(p_h, in_proj_w + (size_t)i * 384 * 128,
                                 in_proj_b + i * 384, p_qkv);
        attn_kernel<<<dim3(4, NB), 128>>>();
        proj_ln_kernel<<<512, 128>>>(p_attno, out_w + (size_t)i * 128 * 128,
                                     out_b + i * 128, ln1_w + i * 128, ln1_b + i * 128, p_h);
        ffn_ln_kernel<<<512, 128>>>(lin1_w + (size_t)i * 128 * 128, lin1_b + i * 128,
                                    lin2_w + (size_t)i * 128 * 128, lin2_b + i * 128,
                                    ln2_w + i * 128, ln2_b + i * 128, p_h);
    }

    topk_kernel<<<NB, 128>>>(attn_w, attn_b);
    cudaMemsetAsync(d_out, 0, (size_t)out_size * sizeof(float), 0);
    scatter_kernel<<<dim3(16, NB), 128>>>(amp_w, amp_b, pos_w, pos_b,
                                          atom_w, atom_b, dmat, out);
}

// round 9
// speedup vs baseline: 2.5397x; 1.5855x over previous
#include <cuda_runtime.h>
#include <math.h>
#include <float.h>

#define NB 32
#define NS 32768
#define NF 128
#define DM 128

// ------------------------- scratch (device globals) -------------------------
__device__ float2 g_twid[512];            // exp(-2*pi*i*k/1024)
__device__ float2 g_P[64 * 1024];         // conj(FFT(w_2c - i w_2c+1)), scrambled
__device__ float g_ewT[161 * 128];        // transposed embed weights
__device__ float g_chunk[NB * NF * DM];
__device__ float g_h[NB * NF * DM];
__device__ float g_qkv[NB * NF * 384];
__device__ float g_attno[NB * NF * DM];
__device__ int   g_topidx[NB * 16];
__device__ float g_topval[NB * 16];

// ------------------------- butterflies ---------------------------------------
__device__ __forceinline__ void bf_dif(float& ar, float& ai, float& br, float& bi, float2 w)
{
    float xr = ar - br, xi = ai - bi;
    ar += br; ai += bi;
    br = xr * w.x - xi * w.y;
    bi = xr * w.y + xi * w.x;
}
__device__ __forceinline__ void bf_dit(float& ar, float& ai, float& br, float& bi, float2 w)
{
    // applies conj(w) to b, then sum/diff
    float tr = br * w.x + bi * w.y;
    float ti = bi * w.x - br * w.y;
    br = ar - tr; bi = ai - ti;
    ar += tr; ai += ti;
}

// ------------------------- forward 1024-pt DIF (in-place, natural->bitrev) ---
// 256 threads. smem re/im must be 16B aligned. Caller syncs before entry.
__device__ __forceinline__ void fft1024_dif(float* re, float* im, const float2* tw, int tid)
{
    {   // stages h=512, 256   (lane-consecutive: conflict-free)
        int r = tid;
        float ar = re[r],       ai = im[r];
        float br = re[r + 256], bi = im[r + 256];
        float cr = re[r + 512], ci = im[r + 512];
        float dr = re[r + 768], di = im[r + 768];
        bf_dif(ar, ai, cr, ci, tw[r]);
        bf_dif(br, bi, dr, di, tw[r + 256]);
        float2 v = tw[2 * r];
        bf_dif(ar, ai, br, bi, v);
        bf_dif(cr, ci, dr, di, v);
        re[r] = ar;       im[r] = ai;
        re[r + 256] = br; im[r + 256] = bi;
        re[r + 512] = cr; im[r + 512] = ci;
        re[r + 768] = dr; im[r + 768] = di;
    }
    __syncthreads();
    {   // stages h=128, 64
        int q = tid >> 6, r = tid & 63, i0 = q * 256 + r;
        float ar = re[i0],       ai = im[i0];
        float br = re[i0 + 64],  bi = im[i0 + 64];
        float cr = re[i0 + 128], ci = im[i0 + 128];
        float dr = re[i0 + 192], di = im[i0 + 192];
        bf_dif(ar, ai, cr, ci, tw[4 * r]);
        bf_dif(br, bi, dr, di, tw[4 * r + 256]);
        float2 v = tw[8 * r];
        bf_dif(ar, ai, br, bi, v);
        bf_dif(cr, ci, dr, di, v);
        re[i0] = ar;       im[i0] = ai;
        re[i0 + 64] = br;  im[i0 + 64] = bi;
        re[i0 + 128] = cr; im[i0 + 128] = ci;
        re[i0 + 192] = dr; im[i0 + 192] = di;
    }
    __syncthreads();
    {   // stages h=32,16,8,4 (shuffle), 2,1 (in-thread); thread t holds 4t..4t+3
        float4 R = ((const float4*)re)[tid];
        float4 I = ((const float4*)im)[tid];
        float vr[4] = {R.x, R.y, R.z, R.w};
        float vi[4] = {I.x, I.y, I.z, I.w};
#pragma unroll
        for (int s = 3; s >= 0; s--) {
            const int mask = 1 << s;
            const int step = 128 >> s;                 // 512/h, h = 4*mask
            const int kb = 4 * (tid & (mask - 1));
            const bool up = (tid & mask) != 0;
#pragma unroll
            for (int j = 0; j < 4; j++) {
                float orr = __shfl_xor_sync(0xffffffffu, vr[j], mask);
                float oii = __shfl_xor_sync(0xffffffffu, vi[j], mask);
                float2 w = tw[(kb + j) * step];
                float sr = vr[j] + orr, si = vi[j] + oii;
                float dr = orr - vr[j], di = oii - vi[j];
                float pr = dr * w.x - di * w.y;
                float pi = dr * w.y + di * w.x;
                vr[j] = up ? pr : sr;
                vi[j] = up ? pi : si;
            }
        }
        {   // h=2: pairs (0,2) W=1; (1,3) W=tw[256]=(0,-1)
            float s0r = vr[0] + vr[2], s0i = vi[0] + vi[2];
            float d0r = vr[0] - vr[2], d0i = vi[0] - vi[2];
            vr[0] = s0r; vi[0] = s0i; vr[2] = d0r; vi[2] = d0i;
            float s1r = vr[1] + vr[3], s1i = vi[1] + vi[3];
            float d1r = vr[1] - vr[3], d1i = vi[1] - vi[3];
            vr[1] = s1r; vi[1] = s1i;
            vr[3] = d1i; vi[3] = -d1r;                 // *(0,-1)
        }
        {   // h=1: W=1
            float t0r = vr[0] + vr[1], t0i = vi[0] + vi[1];
            float t1r = vr[0] - vr[1], t1i = vi[0] - vi[1];
            float t2r = vr[2] + vr[3], t2i = vi[2] + vi[3];
            float t3r = vr[2] - vr[3], t3i = vi[2] - vi[3];
            vr[0] = t0r; vi[0] = t0i; vr[1] = t1r; vi[1] = t1i;
            vr[2] = t2r; vi[2] = t2i; vr[3] = t3r; vi[3] = t3i;
        }
        ((float4*)re)[tid] = make_float4(vr[0], vr[1], vr[2], vr[3]);
        ((float4*)im)[tid] = make_float4(vi[0], vi[1], vi[2], vi[3]);
    }
    __syncthreads();
}

// ------------------------- precompute kernels --------------------------------
__global__ void twid_kernel()
{
    int k = blockIdx.x * 256 + threadIdx.x;
    if (k < 512) {
        double a = -2.0 * 3.14159265358979323846 * (double)k / 1024.0;
        g_twid[k] = make_float2((float)cos(a), (float)sin(a));
    }
}

__global__ __launch_bounds__(256) void filt_kernel(const float* __restrict__ fb)
{
    __shared__ __align__(16) float re[1024], im[1024];
    __shared__ __align__(16) float2 tw[512];
    const int c = blockIdx.x, tid = threadIdx.x;
    tw[tid] = g_twid[tid]; tw[tid + 256] = g_twid[tid + 256];
    for (int i = tid; i < 1024; i += 256) {
        re[i] = (i < 512) ? fb[(size_t)(2 * c) * 512 + i] : 0.f;
        im[i] = (i < 512) ? -fb[(size_t)(2 * c + 1) * 512 + i] : 0.f;
    }
    __syncthreads();
    fft1024_dif(re, im, tw, tid);
    for (int i = tid; i < 1024; i += 256)
        g_P[(size_t)c * 1024 + i] = make_float2(re[i], -im[i]);
}

__global__ void ewt_kernel(const float* __restrict__ ew)
{
    int i = blockIdx.x * 256 + threadIdx.x;
    if (i < 161 * 128) {
        int j = i >> 7, c = i & 127;
        g_ewT[j * 128 + c] = ew[(size_t)c * 161 + j];
    }
}

// ------------------------- FFT conv + |.| + pool -----------------------------
// CTA (seg, b): y[t], t in [512 seg, 512 seg + 512), all 128 channels.
__global__ __launch_bounds__(256) void conv_fft_kernel(const float* __restrict__ x)
{
    __shared__ __align__(16) float uRe[1024], uIm[1024], zRe[1024], zIm[1024];
    __shared__ __align__(16) float2 tw[512];
    __shared__ __align__(16) float2 twA[124];   // [stage][j][i], conflict-free
    __shared__ float cs0[128], cs1[128];
    __shared__ float wpart[8][4];
    const int seg = blockIdx.x, b = blockIdx.y;
    const int tid = threadIdx.x, w = tid >> 5, lane = tid & 31;

    tw[tid] = g_twid[tid]; tw[tid + 256] = g_twid[tid + 256];
    // compact twiddle table: entry offA(s)+(j<<s)+i = g_twid[(4i+j)*(128>>s)]
    if (tid < 124) {
        int e = tid, s, base;
        if (e < 4)       { s = 0; base = 0; }
        else if (e < 12) { s = 1; base = 4; }
        else if (e < 28) { s = 2; base = 12; }
        else if (e < 60) { s = 3; base = 28; }
        else             { s = 4; base = 60; }
        int r = e - base;
        int j = r >> s;
        int i = r & ((1 << s) - 1);
        twA[e] = g_twid[(4 * i + j) * (128 >> s)];
    }
    const float* xb = x + (size_t)b * NS;
    const int base = seg * 512 - 256;
    for (int i = tid; i < 1024; i += 256) {
        int g = base + i;
        uRe[i] = (g >= 0 && g < NS) ? xb[g] : 0.f;
        uIm[i] = 0.f;
    }
    if (tid < 128) { cs0[tid] = 0.f; cs1[tid] = 0.f; }
    __syncthreads();
    fft1024_dif(uRe, uIm, tw, tid);

    // hoist loop invariants into registers
    float ur[4], ui[4];
    {
        float4 R = ((const float4*)uRe)[tid];
        float4 I = ((const float4*)uIm)[tid];
        ur[0] = R.x; ur[1] = R.y; ur[2] = R.z; ur[3] = R.w;
        ui[0] = I.x; ui[1] = I.y; ui[2] = I.z; ui[3] = I.w;
    }
    const int rB = tid & 127;
    const float2 wb1 = tw[4 * rB];
    const float2 wb2 = tw[2 * rB];
    const float2 wb3 = tw[2 * rB + 256];
    const float2 wc1 = tw[tid];
    const float2 wc2 = tw[tid + 256];

    for (int p = 0; p < 64; p++) {
        const float4* Pp = (const float4*)(g_P + (size_t)p * 1024);
        // ---- trip A: fused pointwise + DIT stages 1,2 (in-thread), 4..64 (shuffle)
        {
            float4 P0 = Pp[2 * tid], P1 = Pp[2 * tid + 1];
            float vr[4], vi[4];
            vr[0] = ur[0] * P0.x - ui[0] * P0.y; vi[0] = ur[0] * P0.y + ui[0] * P0.x;
            vr[1] = ur[1] * P0.z - ui[1] * P0.w; vi[1] = ur[1] * P0.w + ui[1] * P0.z;
            vr[2] = ur[2] * P1.x - ui[2] * P1.y; vi[2] = ur[2] * P1.y + ui[2] * P1.x;
            vr[3] = ur[3] * P1.z - ui[3] * P1.w; vi[3] = ur[3] * P1.w + ui[3] * P1.z;
            {   // h=1 (Wc=1)
                float t0r = vr[0] + vr[1], t0i = vi[0] + vi[1];
                float t1r = vr[0] - vr[1], t1i = vi[0] - vi[1];
                float t2r = vr[2] + vr[3], t2i = vi[2] + vi[3];
                float t3r = vr[2] - vr[3], t3i = vi[2] - vi[3];
                vr[0] = t0r; vi[0] = t0i; vr[1] = t1r; vi[1] = t1i;
                vr[2] = t2r; vi[2] = t2i; vr[3] = t3r; vi[3] = t3i;
            }
            {   // h=2: (0,2) Wc=1; (1,3) Wc=(0,1): tv = (-vi3, vr3)
                float s0r = vr[0] + vr[2], s0i = vi[0] + vi[2];
                float d0r = vr[0] - vr[2], d0i = vi[0] - vi[2];
                vr[0] = s0r; vi[0] = s0i; vr[2] = d0r; vi[2] = d0i;
                float tr = -vi[3], ti = vr[3];
                float nr = vr[1] + tr, ni = vi[1] + ti;
                float mr = vr[1] - tr, mi = vi[1] - ti;
                vr[1] = nr; vi[1] = ni; vr[3] = mr; vi[3] = mi;
            }
#pragma unroll
            for (int s = 0; s < 5; s++) {               // h = 4,8,16,32,64
                const int mask = 1 << s;
                const int offA = 4 * (mask - 1);        // 0,4,12,28,60
                const int ib = tid & (mask - 1);
#pragma unroll
                for (int j = 0; j < 4; j++) {
                    float orr = __shfl_xor_sync(0xffffffffu, vr[j], mask);
                    float oii = __shfl_xor_sync(0xffffffffu, vi[j], mask);
                    float2 tww = twA[offA + (j << s) + ib];
                    const bool up = (tid & mask) != 0;
                    float sr = up ? vr[j] : orr;        // value of x[i+h]
                    float sI = up ? vi[j] : oii;
                    float tr = sr * tww.x + sI * tww.y; // * conj(w)
                    float ti = sI * tww.x - sr * tww.y;
                    float lr = vr[j] + tr, li = vi[j] + ti;   // lower result
                    float ur_ = orr - tr, ui_ = oii - ti;     // upper result
                    vr[j] = up ? ur_ : lr;
                    vi[j] = up ? ui_ : li;
                }
            }
            ((float4*)zRe)[tid] = make_float4(vr[0], vr[1], vr[2], vr[3]);
            ((float4*)zIm)[tid] = make_float4(vi[0], vi[1], vi[2], vi[3]);
        }
        __syncthreads();
        // ---- trip B: DIT stages h=128, 256
        {
            int q = tid >> 7, i0 = q * 512 + rB;
            float ar = zRe[i0],       ai = zIm[i0];
            float br = zRe[i0 + 128], bi = zIm[i0 + 128];
            float cr = zRe[i0 + 256], ci = zIm[i0 + 256];
            float dr = zRe[i0 + 384], di = zIm[i0 + 384];
            bf_dit(ar, ai, br, bi, wb1);
            bf_dit(cr, ci, dr, di, wb1);
            bf_dit(ar, ai, cr, ci, wb2);
            bf_dit(br, bi, dr, di, wb3);
            zRe[i0] = ar;       zIm[i0] = ai;
            zRe[i0 + 128] = br; zIm[i0 + 128] = bi;
            zRe[i0 + 256] = cr; zIm[i0 + 256] = ci;
            zRe[i0 + 384] = dr; zIm[i0 + 384] = di;
        }
        __syncthreads();
        // ---- trip C: stage h=512 (only needed halves) + pooling
        float v0, v1, v2, v3;
        {
            float ar = zRe[tid], ai = zIm[tid];
            float cr = zRe[tid + 512], ci = zIm[tid + 512];
            float tr = cr * wc1.x + ci * wc1.y, ti = ci * wc1.x - cr * wc1.y;
            float y0r = ar + tr, y0i = ai + ti;
            float br = zRe[tid + 256], bi = zIm[tid + 256];
            float dr = zRe[tid + 768], di = zIm[tid + 768];
            tr = dr * wc2.x + di * wc2.y; ti = di * wc2.x - dr * wc2.y;
            float y1r = br + tr, y1i = bi + ti;
            v0 = fabsf(y0r); v1 = fabsf(y0i);
            v2 = fabsf(y1r); v3 = fabsf(y1i);
        }
#pragma unroll
        for (int o = 16; o; o >>= 1) {
            v0 += __shfl_xor_sync(0xffffffffu, v0, o);
            v1 += __shfl_xor_sync(0xffffffffu, v1, o);
            v2 += __shfl_xor_sync(0xffffffffu, v2, o);
            v3 += __shfl_xor_sync(0xffffffffu, v3, o);
        }
        if (lane == 0) { wpart[w][0] = v0; wpart[w][1] = v1; wpart[w][2] = v2; wpart[w][3] = v3; }
        __syncthreads();
        if (tid < 4) {
            float s = 0.f;
#pragma unroll
            for (int ww = 0; ww < 8; ww++) s += wpart[ww][tid];
            if (tid == 0)      cs0[2 * p]     += s;
            else if (tid == 1) cs0[2 * p + 1] += s;
            else if (tid == 2) cs1[2 * p]     += s;
            else               cs1[2 * p + 1] += s;
        }
        __syncthreads();
    }
    const float scale = 1.f / (1024.f * 512.f);
    if (tid < 128) {
        g_chunk[((size_t)b * NF + 2 * seg) * DM + tid]     = cs0[tid] * scale;
        g_chunk[((size_t)b * NF + 2 * seg + 1) * DM + tid] = cs1[tid] * scale;
    }
}

// ---------------- frames + pos-encoding + embed -----------------------------
__global__ __launch_bounds__(128) void embed_kernel(const float* __restrict__ eb)
{
    const int row = blockIdx.x;         // b*128 + t
    const int t = row & 127;
    const int tid = threadIdx.x;
    __shared__ float vec[161];
    {
        float f = g_chunk[(size_t)row * DM + tid];
        if (t > 0) f += g_chunk[(size_t)(row - 1) * DM + tid];
        vec[tid] = f;
    }
    if (tid < 33) {
        float pos = (t == 127) ? 1.0f
                               : __fadd_rn(-1.0f, __fmul_rn((float)t, __fdiv_rn(2.0f, 127.0f)));
        float v;
        if (tid == 0) v = pos;
        else {
            int k = (tid <= 16) ? (tid - 1) : (tid - 17);
            float fr = __fmul_rn(exp2f((float)k), 3.14159274101257324f);
            float prod = __fmul_rn(pos, fr);
            v = (tid <= 16) ? (float)sin((double)prod) : (float)cos((double)prod);
        }
        vec[128 + tid] = v;
    }
    __syncthreads();
    float a0 = eb[tid], a1 = 0.f, a2 = 0.f, a3 = 0.f;
    int j = 0;
#pragma unroll 10
    for (; j + 4 <= 161; j += 4) {
        a0 = fmaf(vec[j],     g_ewT[(j)     * 128 + tid], a0);
        a1 = fmaf(vec[j + 1], g_ewT[(j + 1) * 128 + tid], a1);
        a2 = fmaf(vec[j + 2], g_ewT[(j + 2) * 128 + tid], a2);
        a3 = fmaf(vec[j + 3], g_ewT[(j + 3) * 128 + tid], a3);
    }
    for (; j < 161; j++) a0 = fmaf(vec[j], g_ewT[j * 128 + tid], a0);
    g_h[(size_t)row * DM + tid] = (a0 + a1) + (a2 + a3);
}

// ---------------- qkv linear (K = 128, NO = 3) -------------------------------
__global__ __launch_bounds__(128) void qkv_kernel(const float* __restrict__ in,
                                                  const float* __restrict__ W,
                                                  const float* __restrict__ bias,
                                                  float* __restrict__ out)
{
    const int row0 = blockIdx.x << 3;
    const int tid = threadIdx.x;
    __shared__ __align__(16) float sv[8 * DM];
#pragma unroll
    for (int r = 0; r < 8; r++) sv[r * DM + tid] = in[(size_t)(row0 + r) * DM + tid];
    __syncthreads();
    float acc[3][8];
#pragma unroll
    for (int o = 0; o < 3; o++) {
        float bv = bias[o * DM + tid];
#pragma unroll
        for (int r = 0; r < 8; r++) acc[o][r] = bv;
    }
    const float4* sv4 = (const float4*)sv;
    const float4* W4 = (const float4*)W;
    for (int j4 = 0; j4 < 32; j4++) {
        float4 wv[3];
#pragma unroll
        for (int o = 0; o < 3; o++) wv[o] = W4[(size_t)(o * DM + tid) * 32 + j4];
#pragma unroll
        for (int r = 0; r < 8; r++) {
            float4 xv = sv4[r * 32 + j4];
#pragma unroll
            for (int o = 0; o < 3; o++) {
                acc[o][r] = fmaf(wv[o].x, xv.x, acc[o][r]);
                acc[o][r] = fmaf(wv[o].y, xv.y, acc[o][r]);
                acc[o][r] = fmaf(wv[o].z, xv.z, acc[o][r]);
                acc[o][r] = fmaf(wv[o].w, xv.w, acc[o][r]);
            }
        }
    }
#pragma unroll
    for (int r = 0; r < 8; r++)
#pragma unroll
        for (int o = 0; o < 3; o++)
            out[(size_t)(row0 + r) * 384 + o * DM + tid] = acc[o][r];
}

// ---------------- LN epilogue (rows resident in CTA) -------------------------
__device__ __forceinline__ void ln_epilogue(float v[8], const float* lnw, const float* lnb,
                                            float* h, int row0, int tid)
{
    __shared__ float red[4][8];
    const int w = tid >> 5;
    float mean[8];
#pragma unroll
    for (int r = 0; r < 8; r++) {
        float s = v[r];
#pragma unroll
        for (int o = 16; o; o >>= 1) s += __shfl_xor_sync(0xffffffffu, s, o);
        if ((tid & 31) == 0) red[w][r] = s;
    }
    __syncthreads();
#pragma unroll
    for (int r = 0; r < 8; r++)
        mean[r] = (red[0][r] + red[1][r] + red[2][r] + red[3][r]) * 0.0078125f;
    __syncthreads();
#pragma unroll
    for (int r = 0; r < 8; r++) {
        float dv = v[r] - mean[r];
        float s = dv * dv;
#pragma unroll
        for (int o = 16; o; o >>= 1) s += __shfl_xor_sync(0xffffffffu, s, o);
        if ((tid & 31) == 0) red[w][r] = s;
        v[r] = dv;
    }
    __syncthreads();
    float lw = lnw[tid], lb = lnb[tid];
#pragma unroll
    for (int r = 0; r < 8; r++) {
        float var = (red[0][r] + red[1][r] + red[2][r] + red[3][r]) * 0.0078125f;
        h[(size_t)(row0 + r) * DM + tid] = v[r] * (1.f / sqrtf(var + 1e-5f)) * lw + lb;
    }
}

// ---------------- out-proj + residual + LN -----------------------------------
__global__ __launch_bounds__(128) void proj_ln_kernel(const float* __restrict__ in,
                                                      const float* __restrict__ W,
                                                      const float* __restrict__ bias,
                                                      const float* __restrict__ lnw,
                                                      const float* __restrict__ lnb,
                                                      float* __restrict__ h)
{
    const int row0 = blockIdx.x << 3;
    const int tid = threadIdx.x;
    __shared__ __align__(16) float sv[8 * DM];
#pragma unroll
    for (int r = 0; r < 8; r++) sv[r * DM + tid] = in[(size_t)(row0 + r) * DM + tid];
    __syncthreads();
    float acc[8];
    float bv = bias[tid];
#pragma unroll
    for (int r = 0; r < 8; r++) acc[r] = bv;
    const float4* sv4 = (const float4*)sv;
    const float4* W4 = (const float4*)W;
    for (int j4 = 0; j4 < 32; j4++) {
        float4 wv = W4[(size_t)tid * 32 + j4];
#pragma unroll
        for (int r = 0; r < 8; r++) {
            float4 xv = sv4[r * 32 + j4];
            acc[r] = fmaf(wv.x, xv.x, acc[r]);
            acc[r] = fmaf(wv.y, xv.y, acc[r]);
            acc[r] = fmaf(wv.z, xv.z, acc[r]);
            acc[r] = fmaf(wv.w, xv.w, acc[r]);
        }
    }
    float v[8];
#pragma unroll
    for (int r = 0; r < 8; r++) v[r] = h[(size_t)(row0 + r) * DM + tid] + acc[r];
    ln_epilogue(v, lnw, lnb, h, row0, tid);
}

// ---------------- FFN (2 linears + relu) + residual + LN ---------------------
__global__ __launch_bounds__(128) void ffn_ln_kernel(const float* __restrict__ W1,
                                                     const float* __restrict__ b1,
                                                     const float* __restrict__ W2,
                                                     const float* __restrict__ b2,
                                                     const float* __restrict__ lnw,
                                                     const float* __restrict__ lnb,
                                                     float* __restrict__ h)
{
    const int row0 = blockIdx.x << 3;
    const int tid = threadIdx.x;
    __shared__ __align__(16) float sv[8 * DM];
    __shared__ __align__(16) float s1[8 * DM];
#pragma unroll
    for (int r = 0; r < 8; r++) sv[r * DM + tid] = h[(size_t)(row0 + r) * DM + tid];
    __syncthreads();
    float acc[8];
    {
        float bv = b1[tid];
#pragma unroll
        for (int r = 0; r < 8; r++) acc[r] = bv;
        const float4* sv4 = (const float4*)sv;
        const float4* W4 = (const float4*)W1;
        for (int j4 = 0; j4 < 32; j4++) {
            float4 wv = W4[(size_t)tid * 32 + j4];
#pragma unroll
            for (int r = 0; r < 8; r++) {
                float4 xv = sv4[r * 32 + j4];
                acc[r] = fmaf(wv.x, xv.x, acc[r]);
                acc[r] = fmaf(wv.y, xv.y, acc[r]);
                acc[r] = fmaf(wv.z, xv.z, acc[r]);
                acc[r] = fmaf(wv.w, xv.w, acc[r]);
            }
        }
    }
#pragma unroll
    for (int r = 0; r < 8; r++) s1[r * DM + tid] = fmaxf(acc[r], 0.f);
    __syncthreads();
    {
        float bv = b2[tid];
#pragma unroll
        for (int r = 0; r < 8; r++) acc[r] = bv;
        const float4* s14 = (const float4*)s1;
        const float4* W4 = (const float4*)W2;
        for (int j4 = 0; j4 < 32; j4++) {
            float4 wv = W4[(size_t)tid * 32 + j4];
#pragma unroll
            for (int r = 0; r < 8; r++) {
                float4 xv = s14[r * 32 + j4];
                acc[r] = fmaf(wv.x, xv.x, acc[r]);
                acc[r] = fmaf(wv.y, xv.y, acc[r]);
                acc[r] = fmaf(wv.z, xv.z, acc[r]);
                acc[r] = fmaf(wv.w, xv.w, acc[r]);
            }
        }
    }
    float v[8];
#pragma unroll
    for (int r = 0; r < 8; r++) v[r] = sv[r * DM + tid] + acc[r];
    ln_epilogue(v, lnw, lnb, h, row0, tid);
}

// ---------------- attention (one block per (head, batch)) -------------------
__global__ __launch_bounds__(128) void attn_kernel()
{
    const int hd = blockIdx.x, b = blockIdx.y;
    const int tid = threadIdx.x;
    __shared__ __align__(16) float ks[NF * 32];
    __shared__ __align__(16) float vs[NF * 32];
    const float* base = g_qkv + (size_t)b * NF * 384;

    for (int idx = tid; idx < NF * 32; idx += 128) {
        int j = idx >> 5, i = idx & 31;
        ks[idx] = base[j * 384 + 128 + hd * 32 + i];
        vs[idx] = base[j * 384 + 256 + hd * 32 + i];
    }
    float q[32];
    {
        const float4* qp = (const float4*)(base + (size_t)tid * 384 + hd * 32);
#pragma unroll
        for (int i = 0; i < 8; i++) {
            float4 v = qp[i];
            q[4 * i] = v.x; q[4 * i + 1] = v.y; q[4 * i + 2] = v.z; q[4 * i + 3] = v.w;
        }
    }
    __syncthreads();

    float o[32];
#pragma unroll
    for (int i = 0; i < 32; i++) o[i] = 0.f;
    float m = -FLT_MAX, l = 0.f;
    const float scale = 0.17677669529663689f;

    for (int j = 0; j < NF; j++) {
        const float4* kp = (const float4*)(ks + j * 32);
        float s = 0.f;
#pragma unroll
        for (int i = 0; i < 8; i++) {
            float4 kv = kp[i];
            s = fmaf(q[4 * i], kv.x, s); s = fmaf(q[4 * i + 1], kv.y, s);
            s = fmaf(q[4 * i + 2], kv.z, s); s = fmaf(q[4 * i + 3], kv.w, s);
        }
        s *= scale;
        float mn = fmaxf(m, s);
        float c = expf(m - mn);
        float p = expf(s - mn);
        l = l * c + p;
        const float4* vp = (const float4*)(vs + j * 32);
#pragma unroll
        for (int i = 0; i < 8; i++) {
            float4 vv = vp[i];
            o[4 * i]     = o[4 * i] * c + p * vv.x;
            o[4 * i + 1] = o[4 * i + 1] * c + p * vv.y;
            o[4 * i + 2] = o[4 * i + 2] * c + p * vv.z;
            o[4 * i + 3] = o[4 * i + 3] * c + p * vv.w;
        }
        m = mn;
    }
    float inv = 1.f / l;
    float* dst = g_attno + (size_t)(b * NF + tid) * DM + hd * 32;
#pragma unroll
    for (int i = 0; i < 32; i++) dst[i] = o[i] * inv;
}

// ---------------- attention scores + top-16 ---------------------------------
__global__ __launch_bounds__(128) void topk_kernel(const float* __restrict__ attn_w,
                                                   const float* __restrict__ attn_b)
{
    const int b = blockIdx.x, tid = threadIdx.x;
    __shared__ float sv[128];
    __shared__ float rv[128];
    __shared__ int ri[128];
    const float4* hp = (const float4*)(g_h + (size_t)(b * NF + tid) * DM);
    const float4* wp = (const float4*)attn_w;
    float s = attn_b[0];
#pragma unroll
    for (int i = 0; i < 32; i++) {
        float4 h4 = hp[i], w4 = wp[i];
        s = fmaf(h4.x, w4.x, s); s = fmaf(h4.y, w4.y, s);
        s = fmaf(h4.z, w4.z, s); s = fmaf(h4.w, w4.w, s);
    }
    sv[tid] = s;
    __syncthreads();
    for (int r = 0; r < 16; r++) {
        rv[tid] = sv[tid]; ri[tid] = tid;
        __syncthreads();
        for (int off = 64; off; off >>= 1) {
            if (tid < off) {
                float v2 = rv[tid + off]; int i2 = ri[tid + off];
                if (v2 > rv[tid] || (v2 == rv[tid] && i2 < ri[tid])) { rv[tid] = v2; ri[tid] = i2; }
            }
            __syncthreads();
        }
        if (tid == 0) {
            g_topidx[b * 16 + r] = ri[0];
            g_topval[b * 16 + r] = rv[0];
            sv[ri[0]] = -FLT_MAX;
        }
        __syncthreads();
    }
}

// ---------------- head: amp, pos/atom argmax, scatter -----------------------
__global__ __launch_bounds__(128) void scatter_kernel(const float* __restrict__ amp_w,
                                                      const float* __restrict__ amp_b,
                                                      const float* __restrict__ pos_w,
                                                      const float* __restrict__ pos_b,
                                                      const float* __restrict__ atom_w,
                                                      const float* __restrict__ atom_b,
                                                      const float* __restrict__ dmat,
                                                      float* __restrict__ out)
{
    const int rk = blockIdx.x, b = blockIdx.y, tid = threadIdx.x;
    __shared__ __align__(16) float vec[128];
    __shared__ float rv[128];
    __shared__ int ri[128];
    __shared__ float amp_s;
    __shared__ int jstar_s, astar_s;

    int id = g_topidx[b * 16 + rk];
    float val = g_topval[b * 16 + rk];
    vec[tid] = g_h[(size_t)(b * NF + id) * DM + tid] * val;
    __syncthreads();

    rv[tid] = vec[tid] * amp_w[tid];
    __syncthreads();
    for (int off = 64; off; off >>= 1) {
        if (tid < off) rv[tid] += rv[tid + off];
        __syncthreads();
    }
    if (tid == 0) amp_s = fmaxf(rv[0] + amp_b[0], 0.f);
    __syncthreads();

    const float4* vp = (const float4*)vec;

    float bv = -FLT_MAX; int bi = 1 << 30;
#pragma unroll
    for (int q = 0; q < 4; q++) {
        int o = q * 128 + tid;
        const float4* wp = (const float4*)(pos_w + (size_t)o * DM);
        float lg = pos_b[o];
#pragma unroll
        for (int i = 0; i < 32; i++) {
            float4 w4 = wp[i], v4 = vp[i];
            lg = fmaf(w4.x, v4.x, lg); lg = fmaf(w4.y, v4.y, lg);
            lg = fmaf(w4.z, v4.z, lg); lg = fmaf(w4.w, v4.w, lg);
        }
        if (lg > bv || (lg == bv && o < bi)) { bv = lg; bi = o; }
    }
    rv[tid] = bv; ri[tid] = bi;
    __syncthreads();
    for (int off = 64; off; off >>= 1) {
        if (tid < off) {
            float v2 = rv[tid + off]; int i2 = ri[tid + off];
            if (v2 > rv[tid] || (v2 == rv[tid] && i2 < ri[tid])) { rv[tid] = v2; ri[tid] = i2; }
        }
        __syncthreads();
    }
    if (tid == 0) jstar_s = ri[0];
    __syncthreads();

    bv = -FLT_MAX; bi = 1 << 30;
#pragma unroll
    for (int q = 0; q < 2; q++) {
        int o = q * 128 + tid;
        const float4* wp = (const float4*)(atom_w + (size_t)o * DM);
        float lg = atom_b[o];
#pragma unroll
        for (int i = 0; i < 32; i++) {
            float4 w4 = wp[i], v4 = vp[i];
            lg = fmaf(w4.x, v4.x, lg); lg = fmaf(w4.y, v4.y, lg);
            lg = fmaf(w4.z, v4.z, lg); lg = fmaf(w4.w, v4.w, lg);
        }
        if (lg > bv || (lg == bv && o < bi)) { bv = lg; bi = o; }
    }
    rv[tid] = bv; ri[tid] = bi;
    __syncthreads();
    for (int off = 64; off; off >>= 1) {
        if (tid < off) {
            float v2 = rv[tid + off]; int i2 = ri[tid + off];
            if (v2 > rv[tid] || (v2 == rv[tid] && i2 < ri[tid])) { rv[tid] = v2; ri[tid] = i2; }
        }
        __syncthreads();
    }
    if (tid == 0) astar_s = ri[0];
    __syncthreads();

    float amp = amp_s;
    int p = jstar_s * 64;
    int a = astar_s;
    for (int i = tid; i < 256; i += 128) {
        int t = p + i;
        if (t < NS)
            atomicAdd(out + (size_t)b * NS + t, dmat[(size_t)a * 256 + i] * amp);
    }
}

// ---------------------------------------------------------------------------
extern "C" void kernel_launch(void* const* d_in, const int* in_sizes, int n_in,
                              void* d_out, int out_size)
{
    const float* x         = (const float*)d_in[0];
    const float* fb        = (const float*)d_in[1];
    const float* embed_w   = (const float*)d_in[2];
    const float* embed_b   = (const float*)d_in[3];
    const float* in_proj_w = (const float*)d_in[4];
    const float* in_proj_b = (const float*)d_in[5];
    const float* out_w     = (const float*)d_in[6];
    const float* out_b     = (const float*)d_in[7];
    const float* lin1_w    = (const float*)d_in[8];
    const float* lin1_b    = (const float*)d_in[9];
    const float* lin2_w    = (const float*)d_in[10];
    const float* lin2_b    = (const float*)d_in[11];
    const float* ln1_w     = (const float*)d_in[12];
    const float* ln1_b     = (const float*)d_in[13];
    const float* ln2_w     = (const float*)d_in[14];
    const float* ln2_b     = (const float*)d_in[15];
    const float* attn_w    = (const float*)d_in[16];
    const float* attn_b    = (const float*)d_in[17];
    const float* amp_w     = (const float*)d_in[18];
    const float* amp_b     = (const float*)d_in[19];
    const float* pos_w     = (const float*)d_in[20];
    const float* pos_b     = (const float*)d_in[21];
    const float* atom_w    = (const float*)d_in[22];
    const float* atom_b    = (const float*)d_in[23];
    const float* dmat      = (const float*)d_in[24];
    float* out = (float*)d_out;

    float *p_h, *p_qkv, *p_attno;
    cudaGetSymbolAddress((void**)&p_h, g_h);
    cudaGetSymbolAddress((void**)&p_qkv, g_qkv);
    cudaGetSymbolAddress((void**)&p_attno, g_attno);

    twid_kernel<<<2, 256>>>();
    ewt_kernel<<<(161 * 128 + 255) / 256, 256>>>(embed_w);
    filt_kernel<<<64, 256>>>(fb);
    conv_fft_kernel<<<dim3(64, NB), 256>>>(x);

    embed_kernel<<<NB * NF, 128>>>(embed_b);

    for (int i = 0; i < 6; i++) {
        qkv_kernel<<<512, 128>>>(p_h, in_proj_w + (size_t)i * 384 * 128,
                                 in_proj_b + i * 384, p_qkv);
        attn_kernel<<<dim3(4, NB), 128>>>();
        proj_ln_kernel<<<512, 128>>>(p_attno, out_w + (size_t)i * 128 * 128,
                                     out_b + i * 128, ln1_w + i * 128, ln1_b + i * 128, p_h);
        ffn_ln_kernel<<<512, 128>>>(lin1_w + (size_t)i * 128 * 128, lin1_b + i * 128,
                                    lin2_w + (size_t)i * 128 * 128, lin2_b + i * 128,
                                    ln2_w + i * 128, ln2_b + i * 128, p_h);
    }

    topk_kernel<<<NB, 128>>>(attn_w, attn_b);
    cudaMemsetAsync(d_out, 0, (size_t)out_size * sizeof(float), 0);
    scatter_kernel<<<dim3(16, NB), 128>>>(amp_w, amp_b, pos_w, pos_b,
                                          atom_w, atom_b, dmat, out);
}

// round 10
// speedup vs baseline: 2.8567x; 1.1248x over previous
#include <cuda_runtime.h>
#include <math.h>
#include <float.h>

#define NB 32
#define NS 32768
#define NF 128
#define DM 128

// ------------------------- scratch (device globals) -------------------------
__device__ float2 g_twid[512];            // exp(-2*pi*i*k/1024)
__device__ float2 g_P[64 * 1024];         // conj(FFT(w_2c - i w_2c+1)), scrambled
__device__ float g_ewT[161 * 128];        // transposed embed weights
__device__ float g_chunk[NB * NF * DM];
__device__ float g_h[NB * NF * DM];
__device__ float g_qkv[NB * NF * 384];
__device__ float g_attno[NB * NF * DM];
__device__ int   g_topidx[NB * 16];
__device__ float g_topval[NB * 16];

// ------------------------- butterflies ---------------------------------------
__device__ __forceinline__ void bf_dif(float& ar, float& ai, float& br, float& bi, float2 w)
{
    float xr = ar - br, xi = ai - bi;
    ar += br; ai += bi;
    br = xr * w.x - xi * w.y;
    bi = xr * w.y + xi * w.x;
}
__device__ __forceinline__ void bf_dit(float& ar, float& ai, float& br, float& bi, float2 w)
{
    // applies conj(w) to b, then sum/diff
    float tr = br * w.x + bi * w.y;
    float ti = bi * w.x - br * w.y;
    br = ar - tr; bi = ai - ti;
    ar += tr; ai += ti;
}

// ------------------------- forward 1024-pt DIF (in-place, natural->bitrev) ---
__device__ __forceinline__ void fft1024_dif(float* re, float* im, const float2* tw, int tid)
{
    {   // stages h=512, 256
        int r = tid;
        float ar = re[r],       ai = im[r];
        float br = re[r + 256], bi = im[r + 256];
        float cr = re[r + 512], ci = im[r + 512];
        float dr = re[r + 768], di = im[r + 768];
        bf_dif(ar, ai, cr, ci, tw[r]);
        bf_dif(br, bi, dr, di, tw[r + 256]);
        float2 v = tw[2 * r];
        bf_dif(ar, ai, br, bi, v);
        bf_dif(cr, ci, dr, di, v);
        re[r] = ar;       im[r] = ai;
        re[r + 256] = br; im[r + 256] = bi;
        re[r + 512] = cr; im[r + 512] = ci;
        re[r + 768] = dr; im[r + 768] = di;
    }
    __syncthreads();
    {   // stages h=128, 64
        int q = tid >> 6, r = tid & 63, i0 = q * 256 + r;
        float ar = re[i0],       ai = im[i0];
        float br = re[i0 + 64],  bi = im[i0 + 64];
        float cr = re[i0 + 128], ci = im[i0 + 128];
        float dr = re[i0 + 192], di = im[i0 + 192];
        bf_dif(ar, ai, cr, ci, tw[4 * r]);
        bf_dif(br, bi, dr, di, tw[4 * r + 256]);
        float2 v = tw[8 * r];
        bf_dif(ar, ai, br, bi, v);
        bf_dif(cr, ci, dr, di, v);
        re[i0] = ar;       im[i0] = ai;
        re[i0 + 64] = br;  im[i0 + 64] = bi;
        re[i0 + 128] = cr; im[i0 + 128] = ci;
        re[i0 + 192] = dr; im[i0 + 192] = di;
    }
    __syncthreads();
    {   // stages h=32..4 (shuffle), 2,1 (in-thread)
        float4 R = ((const float4*)re)[tid];
        float4 I = ((const float4*)im)[tid];
        float vr[4] = {R.x, R.y, R.z, R.w};
        float vi[4] = {I.x, I.y, I.z, I.w};
#pragma unroll
        for (int s = 3; s >= 0; s--) {
            const int mask = 1 << s;
            const int step = 128 >> s;
            const int kb = 4 * (tid & (mask - 1));
            const bool up = (tid & mask) != 0;
#pragma unroll
            for (int j = 0; j < 4; j++) {
                float orr = __shfl_xor_sync(0xffffffffu, vr[j], mask);
                float oii = __shfl_xor_sync(0xffffffffu, vi[j], mask);
                float2 w = tw[(kb + j) * step];
                float sr = vr[j] + orr, si = vi[j] + oii;
                float dr = orr - vr[j], di = oii - vi[j];
                float pr = dr * w.x - di * w.y;
                float pi = dr * w.y + di * w.x;
                vr[j] = up ? pr : sr;
                vi[j] = up ? pi : si;
            }
        }
        {
            float s0r = vr[0] + vr[2], s0i = vi[0] + vi[2];
            float d0r = vr[0] - vr[2], d0i = vi[0] - vi[2];
            vr[0] = s0r; vi[0] = s0i; vr[2] = d0r; vi[2] = d0i;
            float s1r = vr[1] + vr[3], s1i = vi[1] + vi[3];
            float d1r = vr[1] - vr[3], d1i = vi[1] - vi[3];
            vr[1] = s1r; vi[1] = s1i;
            vr[3] = d1i; vi[3] = -d1r;
        }
        {
            float t0r = vr[0] + vr[1], t0i = vi[0] + vi[1];
            float t1r = vr[0] - vr[1], t1i = vi[0] - vi[1];
            float t2r = vr[2] + vr[3], t2i = vi[2] + vi[3];
            float t3r = vr[2] - vr[3], t3i = vi[2] - vi[3];
            vr[0] = t0r; vi[0] = t0i; vr[1] = t1r; vi[1] = t1i;
            vr[2] = t2r; vi[2] = t2i; vr[3] = t3r; vi[3] = t3i;
        }
        ((float4*)re)[tid] = make_float4(vr[0], vr[1], vr[2], vr[3]);
        ((float4*)im)[tid] = make_float4(vi[0], vi[1], vi[2], vi[3]);
    }
    __syncthreads();
}

// ------------------------- precompute kernels --------------------------------
__global__ void twid_kernel()
{
    int k = blockIdx.x * 256 + threadIdx.x;
    if (k < 512) {
        double a = -2.0 * 3.14159265358979323846 * (double)k / 1024.0;
        g_twid[k] = make_float2((float)cos(a), (float)sin(a));
    }
}

__global__ __launch_bounds__(256) void filt_kernel(const float* __restrict__ fb)
{
    __shared__ __align__(16) float re[1024], im[1024];
    __shared__ __align__(16) float2 tw[512];
    const int c = blockIdx.x, tid = threadIdx.x;
    tw[tid] = g_twid[tid]; tw[tid + 256] = g_twid[tid + 256];
    for (int i = tid; i < 1024; i += 256) {
        re[i] = (i < 512) ? fb[(size_t)(2 * c) * 512 + i] : 0.f;
        im[i] = (i < 512) ? -fb[(size_t)(2 * c + 1) * 512 + i] : 0.f;
    }
    __syncthreads();
    fft1024_dif(re, im, tw, tid);
    for (int i = tid; i < 1024; i += 256)
        g_P[(size_t)c * 1024 + i] = make_float2(re[i], -im[i]);
}

__global__ void ewt_kernel(const float* __restrict__ ew)
{
    int i = blockIdx.x * 256 + threadIdx.x;
    if (i < 161 * 128) {
        int j = i >> 7, c = i & 127;
        g_ewT[j * 128 + c] = ew[(size_t)c * 161 + j];
    }
}

// ---- trip A: fused pointwise(U*P) + DIT stages 1..64; result to z slot -------
__device__ __forceinline__ void ifft_stageA(const float ur[4], const float ui[4],
                                            const float4* __restrict__ Pp,
                                            const float2* twA, int tid,
                                            float* zr, float* zi)
{
    float4 P0 = Pp[2 * tid], P1 = Pp[2 * tid + 1];
    float vr[4], vi[4];
    vr[0] = ur[0] * P0.x - ui[0] * P0.y; vi[0] = ur[0] * P0.y + ui[0] * P0.x;
    vr[1] = ur[1] * P0.z - ui[1] * P0.w; vi[1] = ur[1] * P0.w + ui[1] * P0.z;
    vr[2] = ur[2] * P1.x - ui[2] * P1.y; vi[2] = ur[2] * P1.y + ui[2] * P1.x;
    vr[3] = ur[3] * P1.z - ui[3] * P1.w; vi[3] = ur[3] * P1.w + ui[3] * P1.z;
    {   // h=1 (Wc=1)
        float t0r = vr[0] + vr[1], t0i = vi[0] + vi[1];
        float t1r = vr[0] - vr[1], t1i = vi[0] - vi[1];
        float t2r = vr[2] + vr[3], t2i = vi[2] + vi[3];
        float t3r = vr[2] - vr[3], t3i = vi[2] - vi[3];
        vr[0] = t0r; vi[0] = t0i; vr[1] = t1r; vi[1] = t1i;
        vr[2] = t2r; vi[2] = t2i; vr[3] = t3r; vi[3] = t3i;
    }
    {   // h=2: (0,2) Wc=1; (1,3) Wc=(0,1)
        float s0r = vr[0] + vr[2], s0i = vi[0] + vi[2];
        float d0r = vr[0] - vr[2], d0i = vi[0] - vi[2];
        vr[0] = s0r; vi[0] = s0i; vr[2] = d0r; vi[2] = d0i;
        float tr = -vi[3], ti = vr[3];
        float nr = vr[1] + tr, ni = vi[1] + ti;
        float mr = vr[1] - tr, mi = vi[1] - ti;
        vr[1] = nr; vi[1] = ni; vr[3] = mr; vi[3] = mi;
    }
#pragma unroll
    for (int s = 0; s < 5; s++) {               // h = 4,8,16,32,64
        const int mask = 1 << s;
        const int offA = 4 * (mask - 1);
        const int ib = tid & (mask - 1);
#pragma unroll
        for (int j = 0; j < 4; j++) {
            float orr = __shfl_xor_sync(0xffffffffu, vr[j], mask);
            float oii = __shfl_xor_sync(0xffffffffu, vi[j], mask);
            float2 tww = twA[offA + (j << s) + ib];
            const bool up = (tid & mask) != 0;
            float sr = up ? vr[j] : orr;
            float sI = up ? vi[j] : oii;
            float tr = sr * tww.x + sI * tww.y;
            float ti = sI * tww.x - sr * tww.y;
            float lr = vr[j] + tr, li = vi[j] + ti;
            float ur_ = orr - tr, ui_ = oii - ti;
            vr[j] = up ? ur_ : lr;
            vi[j] = up ? ui_ : li;
        }
    }
    ((float4*)zr)[tid] = make_float4(vr[0], vr[1], vr[2], vr[3]);
    ((float4*)zi)[tid] = make_float4(vi[0], vi[1], vi[2], vi[3]);
}

// ------------------------- FFT conv + |.| + pool -----------------------------
// CTA (seg, b). Two channel-pairs per iteration; BC phase fully in registers.
__global__ __launch_bounds__(256) void conv_fft_kernel(const float* __restrict__ x)
{
    __shared__ __align__(16) float uRe[1024], uIm[1024];
    __shared__ __align__(16) float zRe[2048], zIm[2048];
    __shared__ __align__(16) float2 tw[512];
    __shared__ __align__(16) float2 twA[124];
    __shared__ float cs0[128], cs1[128];
    __shared__ float wpart[2][4][4];
    const int seg = blockIdx.x, b = blockIdx.y;
    const int tid = threadIdx.x, w = tid >> 5, lane = tid & 31;

    tw[tid] = g_twid[tid]; tw[tid + 256] = g_twid[tid + 256];
    if (tid < 124) {
        int e = tid, s, base0;
        if (e < 4)       { s = 0; base0 = 0; }
        else if (e < 12) { s = 1; base0 = 4; }
        else if (e < 28) { s = 2; base0 = 12; }
        else if (e < 60) { s = 3; base0 = 28; }
        else             { s = 4; base0 = 60; }
        int r = e - base0;
        int j = r >> s;
        int i = r & ((1 << s) - 1);
        twA[e] = g_twid[(4 * i + j) * (128 >> s)];
    }
    const float* xb = x + (size_t)b * NS;
    const int base = seg * 512 - 256;
    for (int i = tid; i < 1024; i += 256) {
        int g = base + i;
        uRe[i] = (g >= 0 && g < NS) ? xb[g] : 0.f;
        uIm[i] = 0.f;
    }
    if (tid < 128) { cs0[tid] = 0.f; cs1[tid] = 0.f; }
    __syncthreads();
    fft1024_dif(uRe, uIm, tw, tid);

    // hoist loop invariants
    float ur[4], ui[4];
    {
        float4 R = ((const float4*)uRe)[tid];
        float4 I = ((const float4*)uIm)[tid];
        ur[0] = R.x; ur[1] = R.y; ur[2] = R.z; ur[3] = R.w;
        ui[0] = I.x; ui[1] = I.y; ui[2] = I.z; ui[3] = I.w;
    }
    const int rB = tid & 127;
    const float2 t4r  = tw[4 * rB];
    const float2 t2r  = tw[2 * rB];
    const float2 t2r2 = tw[2 * rB + 256];
    const float2 t5a = tw[rB], t5b = tw[rB + 128], t5c = tw[rB + 256], t5d = tw[rB + 384];

    for (int p = 0; p < 64; p += 2) {
        // phase A for two pairs
        ifft_stageA(ur, ui, (const float4*)(g_P + (size_t)p * 1024), twA, tid, zRe, zIm);
        ifft_stageA(ur, ui, (const float4*)(g_P + (size_t)(p + 1) * 1024), twA, tid,
                    zRe + 1024, zIm + 1024);
        __syncthreads();

        // phase BC in registers: pair s = tid>>7, row r = rB
        const int s = tid >> 7;
        const float* zr = zRe + (s << 10);
        const float* zi = zIm + (s << 10);
        float xr[8], xi[8];
#pragma unroll
        for (int k = 0; k < 8; k++) { xr[k] = zr[rB + (k << 7)]; xi[k] = zi[rB + (k << 7)]; }
        // stage h=128: pairs (k, k+1), k even
        bf_dit(xr[0], xi[0], xr[1], xi[1], t4r);
        bf_dit(xr[2], xi[2], xr[3], xi[3], t4r);
        bf_dit(xr[4], xi[4], xr[5], xi[5], t4r);
        bf_dit(xr[6], xi[6], xr[7], xi[7], t4r);
        // stage h=256: pairs (0,2),(1,3),(4,6),(5,7)
        bf_dit(xr[0], xi[0], xr[2], xi[2], t2r);
        bf_dit(xr[1], xi[1], xr[3], xi[3], t2r2);
        bf_dit(xr[4], xi[4], xr[6], xi[6], t2r);
        bf_dit(xr[5], xi[5], xr[7], xi[7], t2r2);
        // stage h=512 lower halves only: x[k] += conj(w_k) * x[k+4]
        {
            float tr, ti;
            tr = xr[4] * t5a.x + xi[4] * t5a.y; ti = xi[4] * t5a.x - xr[4] * t5a.y;
            xr[0] += tr; xi[0] += ti;
            tr = xr[5] * t5b.x + xi[5] * t5b.y; ti = xi[5] * t5b.x - xr[5] * t5b.y;
            xr[1] += tr; xi[1] += ti;
            tr = xr[6] * t5c.x + xi[6] * t5c.y; ti = xi[6] * t5c.x - xr[6] * t5c.y;
            xr[2] += tr; xi[2] += ti;
            tr = xr[7] * t5d.x + xi[7] * t5d.y; ti = xi[7] * t5d.x - xr[7] * t5d.y;
            xr[3] += tr; xi[3] += ti;
        }
        // pooling: chunk0 = taus [0,256) -> k=0,1; chunk1 = [256,512) -> k=2,3
        float v0 = fabsf(xr[0]) + fabsf(xr[1]);
        float v1 = fabsf(xi[0]) + fabsf(xi[1]);
        float v2 = fabsf(xr[2]) + fabsf(xr[3]);
        float v3 = fabsf(xi[2]) + fabsf(xi[3]);
#pragma unroll
        for (int o = 16; o; o >>= 1) {
            v0 += __shfl_xor_sync(0xffffffffu, v0, o);
            v1 += __shfl_xor_sync(0xffffffffu, v1, o);
            v2 += __shfl_xor_sync(0xffffffffu, v2, o);
            v3 += __shfl_xor_sync(0xffffffffu, v3, o);
        }
        if (lane == 0) {
            wpart[s][w & 3][0] = v0; wpart[s][w & 3][1] = v1;
            wpart[s][w & 3][2] = v2; wpart[s][w & 3][3] = v3;
        }
        __syncthreads();
        if (tid < 8) {
            int pr = tid >> 2, q = tid & 3;
            float sm = wpart[pr][0][q] + wpart[pr][1][q] + wpart[pr][2][q] + wpart[pr][3][q];
            int pp = p + pr;
            if (q == 0)      cs0[2 * pp]     += sm;
            else if (q == 1) cs0[2 * pp + 1] += sm;
            else if (q == 2) cs1[2 * pp]     += sm;
            else             cs1[2 * pp + 1] += sm;
        }
        __syncthreads();
    }
    const float scale = 1.f / (1024.f * 512.f);
    if (tid < 128) {
        g_chunk[((size_t)b * NF + 2 * seg) * DM + tid]     = cs0[tid] * scale;
        g_chunk[((size_t)b * NF + 2 * seg + 1) * DM + tid] = cs1[tid] * scale;
    }
}

// ---------------- frames + pos-encoding + embed (8 rows / block) -------------
__global__ __launch_bounds__(128) void embed_kernel(const float* __restrict__ eb)
{
    const int row0 = blockIdx.x << 3;
    const int tid = threadIdx.x;
    __shared__ float vec[8][161];
    for (int idx = tid; idx < 1024; idx += 128) {
        int r = idx >> 7, ch = idx & 127;
        int row = row0 + r, t = row & 127;
        float f = g_chunk[(size_t)row * DM + ch];
        if (t > 0) f += g_chunk[(size_t)(row - 1) * DM + ch];
        vec[r][ch] = f;
    }
    for (int idx = tid; idx < 264; idx += 128) {
        int r = idx / 33, kk = idx % 33;
        int t = (row0 + r) & 127;
        float pos = (t == 127) ? 1.0f
                               : __fadd_rn(-1.0f, __fmul_rn((float)t, __fdiv_rn(2.0f, 127.0f)));
        float v;
        if (kk == 0) v = pos;
        else {
            int k = (kk <= 16) ? (kk - 1) : (kk - 17);
            float fr = __fmul_rn(exp2f((float)k), 3.14159274101257324f);
            float prod = __fmul_rn(pos, fr);
            v = (kk <= 16) ? (float)sin((double)prod) : (float)cos((double)prod);
        }
        vec[r][128 + kk] = v;
    }
    __syncthreads();
    float acc[8];
    float bv = eb[tid];
#pragma unroll
    for (int r = 0; r < 8; r++) acc[r] = bv;
    for (int j = 0; j < 161; j++) {
        float wv = g_ewT[j * 128 + tid];
#pragma unroll
        for (int r = 0; r < 8; r++) acc[r] = fmaf(vec[r][j], wv, acc[r]);
    }
#pragma unroll
    for (int r = 0; r < 8; r++)
        g_h[(size_t)(row0 + r) * DM + tid] = acc[r];
}

// ---------------- qkv linear (K = 128, NO = 3) -------------------------------
__global__ __launch_bounds__(128) void qkv_kernel(const float* __restrict__ in,
                                                  const float* __restrict__ W,
                                                  const float* __restrict__ bias,
                                                  float* __restrict__ out)
{
    const int row0 = blockIdx.x << 3;
    const int tid = threadIdx.x;
    __shared__ __align__(16) float sv[8 * DM];
#pragma unroll
    for (int r = 0; r < 8; r++) sv[r * DM + tid] = in[(size_t)(row0 + r) * DM + tid];
    __syncthreads();
    float acc[3][8];
#pragma unroll
    for (int o = 0; o < 3; o++) {
        float bv = bias[o * DM + tid];
#pragma unroll
        for (int r = 0; r < 8; r++) acc[o][r] = bv;
    }
    const float4* sv4 = (const float4*)sv;
    const float4* W4 = (const float4*)W;
    for (int j4 = 0; j4 < 32; j4++) {
        float4 wv[3];
#pragma unroll
        for (int o = 0; o < 3; o++) wv[o] = W4[(size_t)(o * DM + tid) * 32 + j4];
#pragma unroll
        for (int r = 0; r < 8; r++) {
            float4 xv = sv4[r * 32 + j4];
#pragma unroll
            for (int o = 0; o < 3; o++) {
                acc[o][r] = fmaf(wv[o].x, xv.x, acc[o][r]);
                acc[o][r] = fmaf(wv[o].y, xv.y, acc[o][r]);
                acc[o][r] = fmaf(wv[o].z, xv.z, acc[o][r]);
                acc[o][r] = fmaf(wv[o].w, xv.w, acc[o][r]);
            }
        }
    }
#pragma unroll
    for (int r = 0; r < 8; r++)
#pragma unroll
        for (int o = 0; o < 3; o++)
            out[(size_t)(row0 + r) * 384 + o * DM + tid] = acc[o][r];
}

// ---------------- LN epilogue (rows resident in CTA) -------------------------
__device__ __forceinline__ void ln_epilogue(float v[8], const float* lnw, const float* lnb,
                                            float* h, int row0, int tid)
{
    __shared__ float red[4][8];
    const int w = tid >> 5;
    float mean[8];
#pragma unroll
    for (int r = 0; r < 8; r++) {
        float s = v[r];
#pragma unroll
        for (int o = 16; o; o >>= 1) s += __shfl_xor_sync(0xffffffffu, s, o);
        if ((tid & 31) == 0) red[w][r] = s;
    }
    __syncthreads();
#pragma unroll
    for (int r = 0; r < 8; r++)
        mean[r] = (red[0][r] + red[1][r] + red[2][r] + red[3][r]) * 0.0078125f;
    __syncthreads();
#pragma unroll
    for (int r = 0; r < 8; r++) {
        float dv = v[r] - mean[r];
        float s = dv * dv;
#pragma unroll
        for (int o = 16; o; o >>= 1) s += __shfl_xor_sync(0xffffffffu, s, o);
        if ((tid & 31) == 0) red[w][r] = s;
        v[r] = dv;
    }
    __syncthreads();
    float lw = lnw[tid], lb = lnb[tid];
#pragma unroll
    for (int r = 0; r < 8; r++) {
        float var = (red[0][r] + red[1][r] + red[2][r] + red[3][r]) * 0.0078125f;
        h[(size_t)(row0 + r) * DM + tid] = v[r] * (1.f / sqrtf(var + 1e-5f)) * lw + lb;
    }
}

// ---------------- out-proj + residual + LN -----------------------------------
__global__ __launch_bounds__(128) void proj_ln_kernel(const float* __restrict__ in,
                                                      const float* __restrict__ W,
                                                      const float* __restrict__ bias,
                                                      const float* __restrict__ lnw,
                                                      const float* __restrict__ lnb,
                                                      float* __restrict__ h)
{
    const int row0 = blockIdx.x << 3;
    const int tid = threadIdx.x;
    __shared__ __align__(16) float sv[8 * DM];
#pragma unroll
    for (int r = 0; r < 8; r++) sv[r * DM + tid] = in[(size_t)(row0 + r) * DM + tid];
    __syncthreads();
    float acc[8];
    float bv = bias[tid];
#pragma unroll
    for (int r = 0; r < 8; r++) acc[r] = bv;
    const float4* sv4 = (const float4*)sv;
    const float4* W4 = (const float4*)W;
    for (int j4 = 0; j4 < 32; j4++) {
        float4 wv = W4[(size_t)tid * 32 + j4];
#pragma unroll
        for (int r = 0; r < 8; r++) {
            float4 xv = sv4[r * 32 + j4];
            acc[r] = fmaf(wv.x, xv.x, acc[r]);
            acc[r] = fmaf(wv.y, xv.y, acc[r]);
            acc[r] = fmaf(wv.z, xv.z, acc[r]);
            acc[r] = fmaf(wv.w, xv.w, acc[r]);
        }
    }
    float v[8];
#pragma unroll
    for (int r = 0; r < 8; r++) v[r] = h[(size_t)(row0 + r) * DM + tid] + acc[r];
    ln_epilogue(v, lnw, lnb, h, row0, tid);
}

// ---------------- FFN (2 linears + relu) + residual + LN ---------------------
__global__ __launch_bounds__(128) void ffn_ln_kernel(const float* __restrict__ W1,
                                                     const float* __restrict__ b1,
                                                     const float* __restrict__ W2,
                                                     const float* __restrict__ b2,
                                                     const float* __restrict__ lnw,
                                                     const float* __restrict__ lnb,
                                                     float* __restrict__ h)
{
    const int row0 = blockIdx.x << 3;
    const int tid = threadIdx.x;
    __shared__ __align__(16) float sv[8 * DM];
    __shared__ __align__(16) float s1[8 * DM];
#pragma unroll
    for (int r = 0; r < 8; r++) sv[r * DM + tid] = h[(size_t)(row0 + r) * DM + tid];
    __syncthreads();
    float acc[8];
    {
        float bv = b1[tid];
#pragma unroll
        for (int r = 0; r < 8; r++) acc[r] = bv;
        const float4* sv4 = (const float4*)sv;
        const float4* W4 = (const float4*)W1;
        for (int j4 = 0; j4 < 32; j4++) {
            float4 wv = W4[(size_t)tid * 32 + j4];
#pragma unroll
            for (int r = 0; r < 8; r++) {
                float4 xv = sv4[r * 32 + j4];
                acc[r] = fmaf(wv.x, xv.x, acc[r]);
                acc[r] = fmaf(wv.y, xv.y, acc[r]);
                acc[r] = fmaf(wv.z, xv.z, acc[r]);
                acc[r] = fmaf(wv.w, xv.w, acc[r]);
            }
        }
    }
#pragma unroll
    for (int r = 0; r < 8; r++) s1[r * DM + tid] = fmaxf(acc[r], 0.f);
    __syncthreads();
    {
        float bv = b2[tid];
#pragma unroll
        for (int r = 0; r < 8; r++) acc[r] = bv;
        const float4* s14 = (const float4*)s1;
        const float4* W4 = (const float4*)W2;
        for (int j4 = 0; j4 < 32; j4++) {
            float4 wv = W4[(size_t)tid * 32 + j4];
#pragma unroll
            for (int r = 0; r < 8; r++) {
                float4 xv = s14[r * 32 + j4];
                acc[r] = fmaf(wv.x, xv.x, acc[r]);
                acc[r] = fmaf(wv.y, xv.y, acc[r]);
                acc[r] = fmaf(wv.z, xv.z, acc[r]);
                acc[r] = fmaf(wv.w, xv.w, acc[r]);
            }
        }
    }
    float v[8];
#pragma unroll
    for (int r = 0; r < 8; r++) v[r] = sv[r * DM + tid] + acc[r];
    ln_epilogue(v, lnw, lnb, h, row0, tid);
}

// ---------------- attention (one block per (head, batch), j-unroll 2) --------
__global__ __launch_bounds__(128) void attn_kernel()
{
    const int hd = blockIdx.x, b = blockIdx.y;
    const int tid = threadIdx.x;
    __shared__ __align__(16) float ks[NF * 32];
    __shared__ __align__(16) float vs[NF * 32];
    const float* base = g_qkv + (size_t)b * NF * 384;

    for (int idx = tid; idx < NF * 32; idx += 128) {
        int j = idx >> 5, i = idx & 31;
        ks[idx] = base[j * 384 + 128 + hd * 32 + i];
        vs[idx] = base[j * 384 + 256 + hd * 32 + i];
    }
    float q[32];
    {
        const float4* qp = (const float4*)(base + (size_t)tid * 384 + hd * 32);
#pragma unroll
        for (int i = 0; i < 8; i++) {
            float4 v = qp[i];
            q[4 * i] = v.x; q[4 * i + 1] = v.y; q[4 * i + 2] = v.z; q[4 * i + 3] = v.w;
        }
    }
    __syncthreads();

    float o[32];
#pragma unroll
    for (int i = 0; i < 32; i++) o[i] = 0.f;
    float m = -FLT_MAX, l = 0.f;
    const float scale = 0.17677669529663689f;

    for (int j = 0; j < NF; j += 2) {
        const float4* kp1 = (const float4*)(ks + j * 32);
        const float4* kp2 = (const float4*)(ks + j * 32 + 32);
        float s1 = 0.f, s2 = 0.f;
#pragma unroll
        for (int i = 0; i < 8; i++) {
            float4 k1 = kp1[i], k2 = kp2[i];
            s1 = fmaf(q[4 * i], k1.x, s1); s2 = fmaf(q[4 * i], k2.x, s2);
            s1 = fmaf(q[4 * i + 1], k1.y, s1); s2 = fmaf(q[4 * i + 1], k2.y, s2);
            s1 = fmaf(q[4 * i + 2], k1.z, s1); s2 = fmaf(q[4 * i + 2], k2.z, s2);
            s1 = fmaf(q[4 * i + 3], k1.w, s1); s2 = fmaf(q[4 * i + 3], k2.w, s2);
        }
        s1 *= scale; s2 *= scale;
        float mn = fmaxf(m, fmaxf(s1, s2));
        float c = expf(m - mn);
        float p1 = expf(s1 - mn);
        float p2 = expf(s2 - mn);
        l = l * c + p1 + p2;
        const float4* vp1 = (const float4*)(vs + j * 32);
        const float4* vp2 = (const float4*)(vs + j * 32 + 32);
#pragma unroll
        for (int i = 0; i < 8; i++) {
            float4 v1 = vp1[i], v2 = vp2[i];
            o[4 * i]     = fmaf(p2, v2.x, fmaf(p1, v1.x, o[4 * i] * c));
            o[4 * i + 1] = fmaf(p2, v2.y, fmaf(p1, v1.y, o[4 * i + 1] * c));
            o[4 * i + 2] = fmaf(p2, v2.z, fmaf(p1, v1.z, o[4 * i + 2] * c));
            o[4 * i + 3] = fmaf(p2, v2.w, fmaf(p1, v1.w, o[4 * i + 3] * c));
        }
        m = mn;
    }
    float inv = 1.f / l;
    float* dst = g_attno + (size_t)(b * NF + tid) * DM + hd * 32;
#pragma unroll
    for (int i = 0; i < 32; i++) dst[i] = o[i] * inv;
}

// ---------------- attention scores + top-16 ---------------------------------
__global__ __launch_bounds__(128) void topk_kernel(const float* __restrict__ attn_w,
                                                   const float* __restrict__ attn_b)
{
    const int b = blockIdx.x, tid = threadIdx.x;
    __shared__ float sv[128];
    __shared__ float rv[128];
    __shared__ int ri[128];
    const float4* hp = (const float4*)(g_h + (size_t)(b * NF + tid) * DM);
    const float4* wp = (const float4*)attn_w;
    float s = attn_b[0];
#pragma unroll
    for (int i = 0; i < 32; i++) {
        float4 h4 = hp[i], w4 = wp[i];
        s = fmaf(h4.x, w4.x, s); s = fmaf(h4.y, w4.y, s);
        s = fmaf(h4.z, w4.z, s); s = fmaf(h4.w, w4.w, s);
    }
    sv[tid] = s;
    __syncthreads();
    for (int r = 0; r < 16; r++) {
        rv[tid] = sv[tid]; ri[tid] = tid;
        __syncthreads();
        for (int off = 64; off; off >>= 1) {
            if (tid < off) {
                float v2 = rv[tid + off]; int i2 = ri[tid + off];
                if (v2 > rv[tid] || (v2 == rv[tid] && i2 < ri[tid])) { rv[tid] = v2; ri[tid] = i2; }
            }
            __syncthreads();
        }
        if (tid == 0) {
            g_topidx[b * 16 + r] = ri[0];
            g_topval[b * 16 + r] = rv[0];
            sv[ri[0]] = -FLT_MAX;
        }
        __syncthreads();
    }
}

// ---------------- head: amp, pos/atom argmax, scatter -----------------------
__global__ __launch_bounds__(128) void scatter_kernel(const float* __restrict__ amp_w,
                                                      const float* __restrict__ amp_b,
                                                      const float* __restrict__ pos_w,
                                                      const float* __restrict__ pos_b,
                                                      const float* __restrict__ atom_w,
                                                      const float* __restrict__ atom_b,
                                                      const float* __restrict__ dmat,
                                                      float* __restrict__ out)
{
    const int rk = blockIdx.x, b = blockIdx.y, tid = threadIdx.x;
    __shared__ __align__(16) float vec[128];
    __shared__ float rv[128];
    __shared__ int ri[128];
    __shared__ float amp_s;
    __shared__ int jstar_s, astar_s;

    int id = g_topidx[b * 16 + rk];
    float val = g_topval[b * 16 + rk];
    vec[tid] = g_h[(size_t)(b * NF + id) * DM + tid] * val;
    __syncthreads();

    rv[tid] = vec[tid] * amp_w[tid];
    __syncthreads();
    for (int off = 64; off; off >>= 1) {
        if (tid < off) rv[tid] += rv[tid + off];
        __syncthreads();
    }
    if (tid == 0) amp_s = fmaxf(rv[0] + amp_b[0], 0.f);
    __syncthreads();

    const float4* vp = (const float4*)vec;

    float bv = -FLT_MAX; int bi = 1 << 30;
#pragma unroll
    for (int q = 0; q < 4; q++) {
        int o = q * 128 + tid;
        const float4* wp = (const float4*)(pos_w + (size_t)o * DM);
        float lg = pos_b[o];
#pragma unroll
        for (int i = 0; i < 32; i++) {
            float4 w4 = wp[i], v4 = vp[i];
            lg = fmaf(w4.x, v4.x, lg); lg = fmaf(w4.y, v4.y, lg);
            lg = fmaf(w4.z, v4.z, lg); lg = fmaf(w4.w, v4.w, lg);
        }
        if (lg > bv || (lg == bv && o < bi)) { bv = lg; bi = o; }
    }
    rv[tid] = bv; ri[tid] = bi;
    __syncthreads();
    for (int off = 64; off; off >>= 1) {
        if (tid < off) {
            float v2 = rv[tid + off]; int i2 = ri[tid + off];
            if (v2 > rv[tid] || (v2 == rv[tid] && i2 < ri[tid])) { rv[tid] = v2; ri[tid] = i2; }
        }
        __syncthreads();
    }
    if (tid == 0) jstar_s = ri[0];
    __syncthreads();

    bv = -FLT_MAX; bi = 1 << 30;
#pragma unroll
    for (int q = 0; q < 2; q++) {
        int o = q * 128 + tid;
        const float4* wp = (const float4*)(atom_w + (size_t)o * DM);
        float lg = atom_b[o];
#pragma unroll
        for (int i = 0; i < 32; i++) {
            float4 w4 = wp[i], v4 = vp[i];
            lg = fmaf(w4.x, v4.x, lg); lg = fmaf(w4.y, v4.y, lg);
            lg = fmaf(w4.z, v4.z, lg); lg = fmaf(w4.w, v4.w, lg);
        }
        if (lg > bv || (lg == bv && o < bi)) { bv = lg; bi = o; }
    }
    rv[tid] = bv; ri[tid] = bi;
    __syncthreads();
    for (int off = 64; off; off >>= 1) {
        if (tid < off) {
            float v2 = rv[tid + off]; int i2 = ri[tid + off];
            if (v2 > rv[tid] || (v2 == rv[tid] && i2 < ri[tid])) { rv[tid] = v2; ri[tid] = i2; }
        }
        __syncthreads();
    }
    if (tid == 0) astar_s = ri[0];
    __syncthreads();

    float amp = amp_s;
    int p = jstar_s * 64;
    int a = astar_s;
    for (int i = tid; i < 256; i += 128) {
        int t = p + i;
        if (t < NS)
            atomicAdd(out + (size_t)b * NS + t, dmat[(size_t)a * 256 + i] * amp);
    }
}

// ---------------------------------------------------------------------------
extern "C" void kernel_launch(void* const* d_in, const int* in_sizes, int n_in,
                              void* d_out, int out_size)
{
    const float* x         = (const float*)d_in[0];
    const float* fb        = (const float*)d_in[1];
    const float* embed_w   = (const float*)d_in[2];
    const float* embed_b   = (const float*)d_in[3];
    const float* in_proj_w = (const float*)d_in[4];
    const float* in_proj_b = (const float*)d_in[5];
    const float* out_w     = (const float*)d_in[6];
    const float* out_b     = (const float*)d_in[7];
    const float* lin1_w    = (const float*)d_in[8];
    const float* lin1_b    = (const float*)d_in[9];
    const float* lin2_w    = (const float*)d_in[10];
    const float* lin2_b    = (const float*)d_in[11];
    const float* ln1_w     = (const float*)d_in[12];
    const float* ln1_b     = (const float*)d_in[13];
    const float* ln2_w     = (const float*)d_in[14];
    const float* ln2_b     = (const float*)d_in[15];
    const float* attn_w    = (const float*)d_in[16];
    const float* attn_b    = (const float*)d_in[17];
    const float* amp_w     = (const float*)d_in[18];
    const float* amp_b     = (const float*)d_in[19];
    const float* pos_w     = (const float*)d_in[20];
    const float* pos_b     = (const float*)d_in[21];
    const float* atom_w    = (const float*)d_in[22];
    const float* atom_b    = (const float*)d_in[23];
    const float* dmat      = (const float*)d_in[24];
    float* out = (float*)d_out;

    float *p_h, *p_qkv, *p_attno;
    cudaGetSymbolAddress((void**)&p_h, g_h);
    cudaGetSymbolAddress((void**)&p_qkv, g_qkv);
    cudaGetSymbolAddress((void**)&p_attno, g_attno);

    twid_kernel<<<2, 256>>>();
    ewt_kernel<<<(161 * 128 + 255) / 256, 256>>>(embed_w);
    filt_kernel<<<64, 256>>>(fb);
    conv_fft_kernel<<<dim3(64, NB), 256>>>(x);

    embed_kernel<<<NB * NF / 8, 128>>>(embed_b);

    for (int i = 0; i < 6; i++) {
        qkv_kernel<<<512, 128>>>(p_h, in_proj_w + (size_t)i * 384 * 128,
                                 in_proj_b + i * 384, p_qkv);
        attn_kernel<<<dim3(4, NB), 128>>>();
        proj_ln_kernel<<<512, 128>>>(p_attno, out_w + (size_t)i * 128 * 128,
                                     out_b + i * 128, ln1_w + i * 128, ln1_b + i * 128, p_h);
        ffn_ln_kernel<<<512, 128>>>(lin1_w + (size_t)i * 128 * 128, lin1_b + i * 128,
                                    lin2_w + (size_t)i * 128 * 128, lin2_b + i * 128,
                                    ln2_w + i * 128, ln2_b + i * 128, p_h);
    }

    topk_kernel<<<NB, 128>>>(attn_w, attn_b);
    cudaMemsetAsync(d_out, 0, (size_t)out_size * sizeof(float), 0);
    scatter_kernel<<<dim3(16, NB), 128>>>(amp_w, amp_b, pos_w, pos_b,
                                          atom_w, atom_b, dmat, out);
}